// round 1
// baseline (speedup 1.0000x reference)
#include <cuda_runtime.h>
#include <cuda_bf16.h>
#include <math.h>

// Problem constants
#define BB 4
#define SS 2048
#define DD 1024
#define HH 16
#define HDIM 64
#define FFN 2048
#define NTOK (BB*SS)          // 8192

// ---------------- scratch (device globals: allocation-free) ----------------
__device__ float g_X   [NTOK * DD];        // 32 MB  activations / residual
__device__ float g_QKV [NTOK * 3 * DD];    // 96 MB
__device__ float g_AO  [NTOK * DD];        // 32 MB  attention output
__device__ float g_O   [NTOK * DD];        // 32 MB  gemm epilogue buffer
__device__ float g_H   [NTOK * FFN];       // 64 MB  ffn hidden
__device__ float g_part[BB * 16 * DD];
__device__ float g_pool[BB * DD];
__device__ float g_hh  [BB * DD];

__device__ __forceinline__ float gelu_exact(float v) {
    return 0.5f * v * (1.0f + erff(v * 0.7071067811865476f));
}

// ---------------- embedding + positional encoding ----------------
// one thread per (row, column-pair)
__global__ void embed_pe_kernel(const int* __restrict__ ids,
                                const float* __restrict__ emb,
                                float* __restrict__ X) {
    int idx = blockIdx.x * blockDim.x + threadIdx.x;   // 0 .. NTOK*512-1
    if (idx >= NTOK * (DD / 2)) return;
    int row = idx >> 9;            // /512
    int p   = idx & 511;           // pair index
    int s   = row & (SS - 1);
    int id  = ids[row];
    // freq = exp(-(2p) * ln(10000)/D)
    float freq = expf(-0.017988946039015358f * (float)p);  // 2*ln(1e4)/1024
    float sv, cv;
    sincosf((float)s * freq, &sv, &cv);
    size_t eo = (size_t)id * DD + 2 * p;
    size_t xo = (size_t)row * DD + 2 * p;
    X[xo]     = emb[eo]     + sv;
    X[xo + 1] = emb[eo + 1] + cv;
}

// ---------------- generic GEMM: C = A(MxK) * W(NxK)^T [+bias][+gelu] -------
// BM=BN=64, BK=32, 256 threads, 4x4 micro-tile. M,N divisible by 64; K by 32.
template<int EPI>   // 0 = none, 1 = +bias, 2 = gelu(+bias)
__global__ void gemm_nt_kernel(const float* __restrict__ A,
                               const float* __restrict__ W,
                               const float* __restrict__ bias,
                               float* __restrict__ C,
                               int M, int N, int K) {
    __shared__ float As[64][33];
    __shared__ float Ws[64][33];
    const int tid = threadIdx.x;
    const int tx = tid & 15, ty = tid >> 4;
    const int m0 = blockIdx.y * 64, n0 = blockIdx.x * 64;
    const int lr = tid >> 3;             // 0..31
    const int lc = (tid & 7) * 4;        // 0..28

    float acc[4][4] = {};

    for (int k0 = 0; k0 < K; k0 += 32) {
        #pragma unroll
        for (int r = 0; r < 64; r += 32) {
            float4 a = *reinterpret_cast<const float4*>(
                A + (size_t)(m0 + lr + r) * K + k0 + lc);
            As[lr + r][lc]     = a.x;
            As[lr + r][lc + 1] = a.y;
            As[lr + r][lc + 2] = a.z;
            As[lr + r][lc + 3] = a.w;
            float4 w = *reinterpret_cast<const float4*>(
                W + (size_t)(n0 + lr + r) * K + k0 + lc);
            Ws[lr + r][lc]     = w.x;
            Ws[lr + r][lc + 1] = w.y;
            Ws[lr + r][lc + 2] = w.z;
            Ws[lr + r][lc + 3] = w.w;
        }
        __syncthreads();
        #pragma unroll
        for (int kk = 0; kk < 32; kk++) {
            float a[4], b[4];
            #pragma unroll
            for (int i = 0; i < 4; i++) a[i] = As[ty * 4 + i][kk];
            #pragma unroll
            for (int j = 0; j < 4; j++) b[j] = Ws[tx * 4 + j][kk];
            #pragma unroll
            for (int i = 0; i < 4; i++)
                #pragma unroll
                for (int j = 0; j < 4; j++)
                    acc[i][j] += a[i] * b[j];
        }
        __syncthreads();
    }

    #pragma unroll
    for (int i = 0; i < 4; i++) {
        int m = m0 + ty * 4 + i;
        #pragma unroll
        for (int j = 0; j < 4; j++) {
            int n = n0 + tx * 4 + j;
            float v = acc[i][j];
            if (EPI >= 1) v += bias[n];
            if (EPI == 2) v = gelu_exact(v);
            C[(size_t)m * N + n] = v;
        }
    }
}

// ---------------- flash attention (fp32, online softmax) ----------------
// grid (S/64, H, B), 256 threads. 64-query tile, 32-key chunks, HD=64.
// thread -> (row = tid/4, sub = tid%4); sub splits 32 keys (8 each) and
// 64 output dims (d = 4*dd + sub).
__global__ void flash_attn_kernel(const float* __restrict__ qkv,
                                  const int* __restrict__ mask,
                                  float* __restrict__ out) {
    __shared__ float Qs[64][65];
    __shared__ float Ks[32][65];
    __shared__ float Vs[32][65];
    __shared__ float Ps[64][33];

    const int b  = blockIdx.z, h = blockIdx.y;
    const int q0 = blockIdx.x * 64;
    const int tid = threadIdx.x;
    const int row = tid >> 2, sub = tid & 3;
    const size_t base = (size_t)b * SS;
    const int qcol = h * HDIM;

    // load Q tile: 64x64 floats, 4 float4 per thread
    #pragma unroll
    for (int it = 0; it < 4; it++) {
        int idx = tid + 256 * it;
        int r = idx >> 4, c = (idx & 15) * 4;
        float4 v = *reinterpret_cast<const float4*>(
            qkv + (base + q0 + r) * (3 * DD) + qcol + c);
        Qs[r][c] = v.x; Qs[r][c + 1] = v.y; Qs[r][c + 2] = v.z; Qs[r][c + 3] = v.w;
    }

    float O[16];
    #pragma unroll
    for (int i = 0; i < 16; i++) O[i] = 0.f;
    float mprev = -1e30f, lsum = 0.f;

    for (int kc = 0; kc < SS; kc += 32) {
        // load K, V chunks (32x64 each): 2 float4 per thread per matrix
        #pragma unroll
        for (int it = 0; it < 2; it++) {
            int idx = tid + 256 * it;
            int r = idx >> 4, c = (idx & 15) * 4;
            const float* src = qkv + (base + kc + r) * (3 * DD);
            float4 kv = *reinterpret_cast<const float4*>(src + DD + qcol + c);
            Ks[r][c] = kv.x; Ks[r][c + 1] = kv.y; Ks[r][c + 2] = kv.z; Ks[r][c + 3] = kv.w;
            float4 vv = *reinterpret_cast<const float4*>(src + 2 * DD + qcol + c);
            Vs[r][c] = vv.x; Vs[r][c + 1] = vv.y; Vs[r][c + 2] = vv.z; Vs[r][c + 3] = vv.w;
        }
        __syncthreads();

        // scores for my 8 keys
        float s[8];
        #pragma unroll
        for (int jj = 0; jj < 8; jj++) s[jj] = 0.f;
        #pragma unroll 8
        for (int d = 0; d < 64; d++) {
            float qv = Qs[row][d];
            #pragma unroll
            for (int jj = 0; jj < 8; jj++)
                s[jj] += qv * Ks[sub * 8 + jj][d];
        }
        float mx = -1e30f;
        #pragma unroll
        for (int jj = 0; jj < 8; jj++) {
            s[jj] *= 0.125f;                       // 1/sqrt(64)
            int kidx = kc + sub * 8 + jj;
            if (mask[b * SS + kidx] == 0) s[jj] = -1e30f;
            mx = fmaxf(mx, s[jj]);
        }
        mx = fmaxf(mx, __shfl_xor_sync(0xffffffffu, mx, 1));
        mx = fmaxf(mx, __shfl_xor_sync(0xffffffffu, mx, 2));
        float mnew  = fmaxf(mprev, mx);
        float alpha = __expf(mprev - mnew);
        float psum = 0.f;
        #pragma unroll
        for (int jj = 0; jj < 8; jj++) {
            float p = __expf(s[jj] - mnew);
            psum += p;
            Ps[row][sub * 8 + jj] = p;
        }
        lsum = lsum * alpha + psum;
        mprev = mnew;
        __syncthreads();

        #pragma unroll
        for (int dd = 0; dd < 16; dd++) O[dd] *= alpha;
        #pragma unroll 4
        for (int j = 0; j < 32; j++) {
            float p = Ps[row][j];
            #pragma unroll
            for (int dd = 0; dd < 16; dd++)
                O[dd] += p * Vs[j][dd * 4 + sub];
        }
        __syncthreads();
    }

    lsum += __shfl_xor_sync(0xffffffffu, lsum, 1);
    lsum += __shfl_xor_sync(0xffffffffu, lsum, 2);
    float inv = 1.0f / lsum;
    #pragma unroll
    for (int dd = 0; dd < 16; dd++)
        out[(base + q0 + row) * DD + qcol + dd * 4 + sub] = O[dd] * inv;
}

// ---------------- residual add + LayerNorm (in-place into X) --------------
__device__ __forceinline__ float block_reduce_256(float v, float* red) {
    __syncthreads();   // protect red[] from previous use
    int t = threadIdx.x;
    #pragma unroll
    for (int o = 16; o > 0; o >>= 1) v += __shfl_down_sync(0xffffffffu, v, o);
    if ((t & 31) == 0) red[t >> 5] = v;
    __syncthreads();
    if (t < 8) {
        v = red[t];
        #pragma unroll
        for (int o = 4; o > 0; o >>= 1) v += __shfl_down_sync(0xffu, v, o);
        if (t == 0) red[0] = v;
    }
    __syncthreads();
    return red[0];
}

__global__ void add_ln_kernel(const float* __restrict__ A,
                              float* __restrict__ X,
                              const float* __restrict__ g,
                              const float* __restrict__ bt) {
    __shared__ float red[32];
    int r = blockIdx.x, t = threadIdx.x;
    const float* a = A + (size_t)r * DD;
    float* x = X + (size_t)r * DD;
    float v[4];
    float sum = 0.f;
    #pragma unroll
    for (int i = 0; i < 4; i++) {
        int d = t + 256 * i;
        v[i] = a[d] + x[d];
        sum += v[i];
    }
    sum = block_reduce_256(sum, red);
    float mu = sum * (1.0f / DD);
    float vs = 0.f;
    #pragma unroll
    for (int i = 0; i < 4; i++) {
        float dl = v[i] - mu;
        vs += dl * dl;
    }
    vs = block_reduce_256(vs, red);
    float rs = rsqrtf(vs * (1.0f / DD) + 1e-5f);
    #pragma unroll
    for (int i = 0; i < 4; i++) {
        int d = t + 256 * i;
        x[d] = (v[i] - mu) * rs * g[d] + bt[d];
    }
}

// ---------------- masked max-pool over sequence ----------------
__global__ void pool_partial_kernel(const float* __restrict__ X,
                                    const int* __restrict__ mask,
                                    float* __restrict__ part) {
    int b = blockIdx.y, ch = blockIdx.x;    // 16 chunks of 128
    int d = threadIdx.x;                    // 1024
    float m = -INFINITY;
    for (int s = 0; s < 128; s++) {
        int srow = ch * 128 + s;
        float val = X[((size_t)b * SS + srow) * DD + d];
        if (mask[b * SS + srow] != 0) m = fmaxf(m, val);
    }
    part[((size_t)b * 16 + ch) * DD + d] = m;
}

__global__ void pool_final_kernel(const float* __restrict__ part,
                                  float* __restrict__ pooled) {
    int b = blockIdx.x, d = threadIdx.x;
    float m = -INFINITY;
    for (int c = 0; c < 16; c++)
        m = fmaxf(m, part[((size_t)b * 16 + c) * DD + d]);
    pooled[b * DD + d] = m;
}

// ---------------- small head FC: out[b][n] = dot(in[b], W[n]) + bias ------
__global__ void head_fc_kernel(const float* __restrict__ in,
                               const float* __restrict__ W,
                               const float* __restrict__ bias,
                               float* __restrict__ out,
                               int K, int apply_gelu) {
    __shared__ float red[4];
    int n = blockIdx.x, b = blockIdx.y, t = threadIdx.x;  // 128 threads
    int N = gridDim.x;
    const float* ip = in + (size_t)b * K;
    const float* wp = W + (size_t)n * K;
    float s = 0.f;
    for (int k = t; k < K; k += 128) s += ip[k] * wp[k];
    #pragma unroll
    for (int o = 16; o > 0; o >>= 1) s += __shfl_down_sync(0xffffffffu, s, o);
    if ((t & 31) == 0) red[t >> 5] = s;
    __syncthreads();
    if (t == 0) {
        float v = red[0] + red[1] + red[2] + red[3] + bias[n];
        if (apply_gelu) v = gelu_exact(v);
        out[b * N + n] = v;
    }
}

// ---------------- launch ----------------
extern "C" void kernel_launch(void* const* d_in, const int* in_sizes, int n_in,
                              void* d_out, int out_size) {
    const int*   x_ids  = (const int*)d_in[0];
    const int*   mask   = (const int*)d_in[1];
    const float* emb    = (const float*)d_in[2];
    const float* qkv_w  = (const float*)d_in[3];
    const float* fc_w   = (const float*)d_in[4];
    const float* fc_b   = (const float*)d_in[5];
    const float* ln1_g  = (const float*)d_in[6];
    const float* ln1_b  = (const float*)d_in[7];
    const float* ffn_w1 = (const float*)d_in[8];
    const float* ffn_b1 = (const float*)d_in[9];
    const float* ffn_w2 = (const float*)d_in[10];
    const float* ffn_b2 = (const float*)d_in[11];
    const float* ln2_g  = (const float*)d_in[12];
    const float* ln2_b  = (const float*)d_in[13];
    const float* pr_w1  = (const float*)d_in[14];
    const float* pr_b1  = (const float*)d_in[15];
    const float* pr_w2  = (const float*)d_in[16];
    const float* pr_b2  = (const float*)d_in[17];
    float* out = (float*)d_out;

    float *X, *QKV, *AO, *O, *Hb, *part, *pool, *hh;
    cudaGetSymbolAddress((void**)&X,    g_X);
    cudaGetSymbolAddress((void**)&QKV,  g_QKV);
    cudaGetSymbolAddress((void**)&AO,   g_AO);
    cudaGetSymbolAddress((void**)&O,    g_O);
    cudaGetSymbolAddress((void**)&Hb,   g_H);
    cudaGetSymbolAddress((void**)&part, g_part);
    cudaGetSymbolAddress((void**)&pool, g_pool);
    cudaGetSymbolAddress((void**)&hh,   g_hh);

    // 1. embedding + positional encoding
    embed_pe_kernel<<<(NTOK * (DD / 2)) / 256, 256>>>(x_ids, emb, X);

    // 2. QKV projection: [8192,1024] x [3072,1024]^T
    gemm_nt_kernel<0><<<dim3(3 * DD / 64, NTOK / 64), 256>>>(
        X, qkv_w, nullptr, QKV, NTOK, 3 * DD, DD);

    // 3. attention
    flash_attn_kernel<<<dim3(SS / 64, HH, BB), 256>>>(QKV, mask, AO);

    // 4. output projection (+bias)
    gemm_nt_kernel<1><<<dim3(DD / 64, NTOK / 64), 256>>>(
        AO, fc_w, fc_b, O, NTOK, DD, DD);

    // 5. residual + LN1 (in-place into X)
    add_ln_kernel<<<NTOK, 256>>>(O, X, ln1_g, ln1_b);

    // 6. FFN up (+bias, gelu)
    gemm_nt_kernel<2><<<dim3(FFN / 64, NTOK / 64), 256>>>(
        X, ffn_w1, ffn_b1, Hb, NTOK, FFN, DD);

    // 7. FFN down (+bias)
    gemm_nt_kernel<1><<<dim3(DD / 64, NTOK / 64), 256>>>(
        Hb, ffn_w2, ffn_b2, O, NTOK, DD, FFN);

    // 8. residual + LN2
    add_ln_kernel<<<NTOK, 256>>>(O, X, ln2_g, ln2_b);

    // 9. masked max-pool
    pool_partial_kernel<<<dim3(16, BB), 1024>>>(X, mask, part);
    pool_final_kernel<<<BB, 1024>>>(part, pool);

    // 10. prediction head
    head_fc_kernel<<<dim3(DD, BB), 128>>>(pool, pr_w1, pr_b1, hh, DD, 1);
    head_fc_kernel<<<dim3(10, BB), 128>>>(hh, pr_w2, pr_b2, out, DD, 0);
}

// round 3
// speedup vs baseline: 3.9854x; 3.9854x over previous
#include <cuda_runtime.h>
#include <cuda_bf16.h>
#include <math.h>
#include <stdint.h>

// Problem constants
#define BB 4
#define SS 2048
#define DD 1024
#define HH 16
#define HDIM 64
#define FFN 2048
#define NTOK (BB*SS)          // 8192

// ---------------- scratch (device globals: allocation-free) ----------------
__device__ float g_X   [NTOK * DD];        // activations / residual
__device__ float g_QKV [NTOK * 3 * DD];
__device__ float g_AO  [NTOK * DD];        // attention output
__device__ float g_O   [NTOK * DD];        // gemm epilogue buffer
__device__ float g_H   [NTOK * FFN];       // ffn hidden
__device__ float g_part[BB * 16 * DD];
__device__ float g_pool[BB * DD];
__device__ float g_hh  [BB * DD];

__device__ __forceinline__ float gelu_exact(float v) {
    return 0.5f * v * (1.0f + erff(v * 0.7071067811865476f));
}

__device__ __forceinline__ float to_tf32(float x) {
    float y;
    asm("cvt.rna.tf32.f32 %0, %1;" : "=f"(y) : "f"(x));
    return y;
}

__device__ __forceinline__ void mma_tf32(float* d, const uint32_t* a, uint32_t b0, uint32_t b1) {
    asm volatile(
        "mma.sync.aligned.m16n8k8.row.col.f32.tf32.tf32.f32 "
        "{%0,%1,%2,%3}, {%4,%5,%6,%7}, {%8,%9}, {%0,%1,%2,%3};\n"
        : "+f"(d[0]), "+f"(d[1]), "+f"(d[2]), "+f"(d[3])
        : "r"(a[0]), "r"(a[1]), "r"(a[2]), "r"(a[3]), "r"(b0), "r"(b1));
}

// ---------------- embedding + positional encoding ----------------
__global__ void embed_pe_kernel(const int* __restrict__ ids,
                                const float* __restrict__ emb,
                                float* __restrict__ X) {
    int idx = blockIdx.x * blockDim.x + threadIdx.x;   // 0 .. NTOK*512-1
    if (idx >= NTOK * (DD / 2)) return;
    int row = idx >> 9;            // /512
    int p   = idx & 511;           // pair index
    int s   = row & (SS - 1);
    int id  = ids[row];
    float freq = expf(-0.017988946039015358f * (float)p);  // 2*ln(1e4)/1024
    float sv, cv;
    sincosf((float)s * freq, &sv, &cv);
    size_t eo = (size_t)id * DD + 2 * p;
    size_t xo = (size_t)row * DD + 2 * p;
    X[xo]     = emb[eo]     + sv;
    X[xo + 1] = emb[eo + 1] + cv;
}

// ---------------- tf32 tensor-core GEMM: C = A(MxK) * W(NxK)^T ------------
// BM=128, BN=128, BK=16, 256 threads (8 warps, 2x4), warp tile 64x32.
template<int EPI>   // 0 = none, 1 = +bias, 2 = gelu(+bias)
__launch_bounds__(256, 2)
__global__ void gemm_tc_kernel(const float* __restrict__ A,
                               const float* __restrict__ W,
                               const float* __restrict__ bias,
                               float* __restrict__ C,
                               int M, int N, int K) {
    __shared__ float As[128][20];   // stride 20 -> conflict-free frag reads
    __shared__ float Ws[128][20];

    const int tid  = threadIdx.x;
    const int lane = tid & 31, warp = tid >> 5;
    const int wm = warp >> 2, wn = warp & 3;       // 2 x 4 warp grid
    const int wrow = wm * 64, wcol = wn * 32;
    const int m0 = blockIdx.y * 128, n0 = blockIdx.x * 128;
    const int g = lane >> 2, tg = lane & 3;

    float acc[4][4][4];
    #pragma unroll
    for (int mt = 0; mt < 4; mt++)
        #pragma unroll
        for (int nt = 0; nt < 4; nt++)
            #pragma unroll
            for (int r = 0; r < 4; r++) acc[mt][nt][r] = 0.f;

    for (int k0 = 0; k0 < K; k0 += 16) {
        __syncthreads();
        #pragma unroll
        for (int i = 0; i < 2; i++) {
            int idx = tid + 256 * i;      // 0..511
            int r = idx >> 2, c = (idx & 3) * 4;
            float4 av = *reinterpret_cast<const float4*>(A + (size_t)(m0 + r) * K + k0 + c);
            As[r][c]     = to_tf32(av.x);
            As[r][c + 1] = to_tf32(av.y);
            As[r][c + 2] = to_tf32(av.z);
            As[r][c + 3] = to_tf32(av.w);
            float4 wv = *reinterpret_cast<const float4*>(W + (size_t)(n0 + r) * K + k0 + c);
            Ws[r][c]     = to_tf32(wv.x);
            Ws[r][c + 1] = to_tf32(wv.y);
            Ws[r][c + 2] = to_tf32(wv.z);
            Ws[r][c + 3] = to_tf32(wv.w);
        }
        __syncthreads();

        #pragma unroll
        for (int ks = 0; ks < 2; ks++) {
            int kk = ks * 8;
            uint32_t af[4][4], bf[4][2];
            #pragma unroll
            for (int mt = 0; mt < 4; mt++) {
                int r = wrow + mt * 16 + g;
                af[mt][0] = __float_as_uint(As[r][kk + tg]);
                af[mt][1] = __float_as_uint(As[r + 8][kk + tg]);
                af[mt][2] = __float_as_uint(As[r][kk + tg + 4]);
                af[mt][3] = __float_as_uint(As[r + 8][kk + tg + 4]);
            }
            #pragma unroll
            for (int nt = 0; nt < 4; nt++) {
                int r = wcol + nt * 8 + g;
                bf[nt][0] = __float_as_uint(Ws[r][kk + tg]);
                bf[nt][1] = __float_as_uint(Ws[r][kk + tg + 4]);
            }
            #pragma unroll
            for (int mt = 0; mt < 4; mt++)
                #pragma unroll
                for (int nt = 0; nt < 4; nt++)
                    mma_tf32(acc[mt][nt], af[mt], bf[nt][0], bf[nt][1]);
        }
    }

    // epilogue
    #pragma unroll
    for (int mt = 0; mt < 4; mt++) {
        int r0 = m0 + wrow + mt * 16 + g;
        #pragma unroll
        for (int nt = 0; nt < 4; nt++) {
            int c = n0 + wcol + nt * 8 + 2 * tg;
            float b0 = 0.f, b1 = 0.f;
            if (EPI >= 1) { b0 = bias[c]; b1 = bias[c + 1]; }
            float v00 = acc[mt][nt][0] + b0, v01 = acc[mt][nt][1] + b1;
            float v10 = acc[mt][nt][2] + b0, v11 = acc[mt][nt][3] + b1;
            if (EPI == 2) {
                v00 = gelu_exact(v00); v01 = gelu_exact(v01);
                v10 = gelu_exact(v10); v11 = gelu_exact(v11);
            }
            *reinterpret_cast<float2*>(C + (size_t)r0 * N + c)       = make_float2(v00, v01);
            *reinterpret_cast<float2*>(C + (size_t)(r0 + 8) * N + c) = make_float2(v10, v11);
        }
    }
}

// ---------------- tf32 flash attention ----------------
// grid (S/64, H, B), 128 threads (4 warps). 64-query tile, 32-key chunks.
// Warp w owns query rows [16w, 16w+16). Qs smem is reused as P (warp-local rows).
__launch_bounds__(128, 4)
__global__ void flash_tc_kernel(const float* __restrict__ qkv,
                                const int* __restrict__ mask,
                                float* __restrict__ out) {
    __shared__ float Qs[64][68];    // Q tile, reused as P after frag extraction
    __shared__ float Ks[32][68];
    __shared__ float Vs[32][72];
    __shared__ int   msk[32];

    const int b = blockIdx.z, h = blockIdx.y;
    const int q0 = blockIdx.x * 64;
    const int tid = threadIdx.x, lane = tid & 31, warp = tid >> 5;
    const int g = lane >> 2, tg = lane & 3;
    const size_t base = (size_t)b * SS;
    const int qcol = h * HDIM;

    // stage Q (scaled by 1/sqrt(HD) = 0.125)
    #pragma unroll
    for (int i = 0; i < 8; i++) {
        int idx = tid + 128 * i;          // 1024 float4
        int r = idx >> 4, c = (idx & 15) * 4;
        float4 v = *reinterpret_cast<const float4*>(
            qkv + (base + q0 + r) * (3 * DD) + qcol + c);
        Qs[r][c]     = to_tf32(v.x * 0.125f);
        Qs[r][c + 1] = to_tf32(v.y * 0.125f);
        Qs[r][c + 2] = to_tf32(v.z * 0.125f);
        Qs[r][c + 3] = to_tf32(v.w * 0.125f);
    }
    __syncthreads();

    // extract Q fragments (held in regs for whole kernel)
    uint32_t qf[8][4];
    #pragma unroll
    for (int ks = 0; ks < 8; ks++) {
        int r = warp * 16 + g, c = ks * 8 + tg;
        qf[ks][0] = __float_as_uint(Qs[r][c]);
        qf[ks][1] = __float_as_uint(Qs[r + 8][c]);
        qf[ks][2] = __float_as_uint(Qs[r][c + 4]);
        qf[ks][3] = __float_as_uint(Qs[r + 8][c + 4]);
    }

    float o[8][4];
    #pragma unroll
    for (int nt = 0; nt < 8; nt++)
        #pragma unroll
        for (int r = 0; r < 4; r++) o[nt][r] = 0.f;
    float mprev0 = -1e30f, mprev1 = -1e30f;
    float l0 = 0.f, l1 = 0.f;

    for (int kc = 0; kc < SS; kc += 32) {
        __syncthreads();    // previous chunk's reads of Ks/Vs done
        #pragma unroll
        for (int i = 0; i < 4; i++) {
            int idx = tid + 128 * i;      // 512 float4 per matrix
            int r = idx >> 4, c = (idx & 15) * 4;
            const float* src = qkv + (base + kc + r) * (3 * DD);
            float4 kv = *reinterpret_cast<const float4*>(src + DD + qcol + c);
            Ks[r][c]     = to_tf32(kv.x);
            Ks[r][c + 1] = to_tf32(kv.y);
            Ks[r][c + 2] = to_tf32(kv.z);
            Ks[r][c + 3] = to_tf32(kv.w);
            float4 vv = *reinterpret_cast<const float4*>(src + 2 * DD + qcol + c);
            Vs[r][c]     = to_tf32(vv.x);
            Vs[r][c + 1] = to_tf32(vv.y);
            Vs[r][c + 2] = to_tf32(vv.z);
            Vs[r][c + 3] = to_tf32(vv.w);
        }
        if (tid < 32) msk[tid] = mask[b * SS + kc + tid];
        __syncthreads();

        // S = Q K^T (scaled)
        float s[4][4];
        #pragma unroll
        for (int nt = 0; nt < 4; nt++)
            #pragma unroll
            for (int r = 0; r < 4; r++) s[nt][r] = 0.f;
        #pragma unroll
        for (int ks = 0; ks < 8; ks++) {
            #pragma unroll
            for (int nt = 0; nt < 4; nt++) {
                uint32_t b0 = __float_as_uint(Ks[nt * 8 + g][ks * 8 + tg]);
                uint32_t b1 = __float_as_uint(Ks[nt * 8 + g][ks * 8 + tg + 4]);
                mma_tf32(s[nt], qf[ks], b0, b1);
            }
        }

        // mask + row max
        float mx0 = -1e30f, mx1 = -1e30f;
        #pragma unroll
        for (int nt = 0; nt < 4; nt++) {
            int c = nt * 8 + 2 * tg;
            if (msk[c] == 0)     { s[nt][0] = -1e30f; s[nt][2] = -1e30f; }
            if (msk[c + 1] == 0) { s[nt][1] = -1e30f; s[nt][3] = -1e30f; }
            mx0 = fmaxf(mx0, fmaxf(s[nt][0], s[nt][1]));
            mx1 = fmaxf(mx1, fmaxf(s[nt][2], s[nt][3]));
        }
        mx0 = fmaxf(mx0, __shfl_xor_sync(0xffffffffu, mx0, 1));
        mx0 = fmaxf(mx0, __shfl_xor_sync(0xffffffffu, mx0, 2));
        mx1 = fmaxf(mx1, __shfl_xor_sync(0xffffffffu, mx1, 1));
        mx1 = fmaxf(mx1, __shfl_xor_sync(0xffffffffu, mx1, 2));

        float mn0 = fmaxf(mprev0, mx0), mn1 = fmaxf(mprev1, mx1);
        float a0 = __expf(mprev0 - mn0), a1 = __expf(mprev1 - mn1);

        float ps0 = 0.f, ps1 = 0.f;
        #pragma unroll
        for (int nt = 0; nt < 4; nt++) {
            s[nt][0] = __expf(s[nt][0] - mn0);
            s[nt][1] = __expf(s[nt][1] - mn0);
            s[nt][2] = __expf(s[nt][2] - mn1);
            s[nt][3] = __expf(s[nt][3] - mn1);
            ps0 += s[nt][0] + s[nt][1];
            ps1 += s[nt][2] + s[nt][3];
            int r = warp * 16 + g, c = nt * 8 + 2 * tg;
            Qs[r][c]     = s[nt][0];
            Qs[r][c + 1] = s[nt][1];
            Qs[r + 8][c]     = s[nt][2];
            Qs[r + 8][c + 1] = s[nt][3];
        }
        l0 = l0 * a0 + ps0;
        l1 = l1 * a1 + ps1;
        mprev0 = mn0; mprev1 = mn1;
        __syncwarp();   // order P writes vs frag reads (warp-local rows)

        // O = O*alpha + P V
        #pragma unroll
        for (int nt = 0; nt < 8; nt++) {
            o[nt][0] *= a0; o[nt][1] *= a0;
            o[nt][2] *= a1; o[nt][3] *= a1;
        }
        #pragma unroll
        for (int ks = 0; ks < 4; ks++) {
            uint32_t af[4];
            int r = warp * 16 + g, c = ks * 8 + tg;
            af[0] = __float_as_uint(Qs[r][c]);
            af[1] = __float_as_uint(Qs[r + 8][c]);
            af[2] = __float_as_uint(Qs[r][c + 4]);
            af[3] = __float_as_uint(Qs[r + 8][c + 4]);
            #pragma unroll
            for (int nt = 0; nt < 8; nt++) {
                uint32_t b0 = __float_as_uint(Vs[ks * 8 + tg][nt * 8 + g]);
                uint32_t b1 = __float_as_uint(Vs[ks * 8 + tg + 4][nt * 8 + g]);
                mma_tf32(o[nt], af, b0, b1);
            }
        }
        __syncwarp();   // P reads done before next chunk rewrites Qs rows
    }

    l0 += __shfl_xor_sync(0xffffffffu, l0, 1);
    l0 += __shfl_xor_sync(0xffffffffu, l0, 2);
    l1 += __shfl_xor_sync(0xffffffffu, l1, 1);
    l1 += __shfl_xor_sync(0xffffffffu, l1, 2);
    float inv0 = 1.0f / l0, inv1 = 1.0f / l1;

    int r0 = q0 + warp * 16 + g;
    #pragma unroll
    for (int nt = 0; nt < 8; nt++) {
        int c = qcol + nt * 8 + 2 * tg;
        *reinterpret_cast<float2*>(out + (base + r0) * DD + c) =
            make_float2(o[nt][0] * inv0, o[nt][1] * inv0);
        *reinterpret_cast<float2*>(out + (base + r0 + 8) * DD + c) =
            make_float2(o[nt][2] * inv1, o[nt][3] * inv1);
    }
}

// ---------------- residual add + LayerNorm (in-place into X) --------------
__device__ __forceinline__ float block_reduce_256(float v, float* red) {
    __syncthreads();
    int t = threadIdx.x;
    #pragma unroll
    for (int o = 16; o > 0; o >>= 1) v += __shfl_down_sync(0xffffffffu, v, o);
    if ((t & 31) == 0) red[t >> 5] = v;
    __syncthreads();
    if (t < 8) {
        v = red[t];
        #pragma unroll
        for (int o = 4; o > 0; o >>= 1) v += __shfl_down_sync(0xffu, v, o);
        if (t == 0) red[0] = v;
    }
    __syncthreads();
    return red[0];
}

__global__ void add_ln_kernel(const float* __restrict__ A,
                              float* __restrict__ X,
                              const float* __restrict__ g,
                              const float* __restrict__ bt) {
    __shared__ float red[32];
    int r = blockIdx.x, t = threadIdx.x;
    const float* a = A + (size_t)r * DD;
    float* x = X + (size_t)r * DD;
    float v[4];
    float sum = 0.f;
    #pragma unroll
    for (int i = 0; i < 4; i++) {
        int d = t + 256 * i;
        v[i] = a[d] + x[d];
        sum += v[i];
    }
    sum = block_reduce_256(sum, red);
    float mu = sum * (1.0f / DD);
    float vs = 0.f;
    #pragma unroll
    for (int i = 0; i < 4; i++) {
        float dl = v[i] - mu;
        vs += dl * dl;
    }
    vs = block_reduce_256(vs, red);
    float rs = rsqrtf(vs * (1.0f / DD) + 1e-5f);
    #pragma unroll
    for (int i = 0; i < 4; i++) {
        int d = t + 256 * i;
        x[d] = (v[i] - mu) * rs * g[d] + bt[d];
    }
}

// ---------------- masked max-pool over sequence ----------------
__global__ void pool_partial_kernel(const float* __restrict__ X,
                                    const int* __restrict__ mask,
                                    float* __restrict__ part) {
    int b = blockIdx.y, ch = blockIdx.x;    // 16 chunks of 128
    int d = threadIdx.x;                    // 1024
    float m = -INFINITY;
    for (int s = 0; s < 128; s++) {
        int srow = ch * 128 + s;
        float val = X[((size_t)b * SS + srow) * DD + d];
        if (mask[b * SS + srow] != 0) m = fmaxf(m, val);
    }
    part[((size_t)b * 16 + ch) * DD + d] = m;
}

__global__ void pool_final_kernel(const float* __restrict__ part,
                                  float* __restrict__ pooled) {
    int b = blockIdx.x, d = threadIdx.x;
    float m = -INFINITY;
    for (int c = 0; c < 16; c++)
        m = fmaxf(m, part[((size_t)b * 16 + c) * DD + d]);
    pooled[b * DD + d] = m;
}

// ---------------- small head FC ----------------
__global__ void head_fc_kernel(const float* __restrict__ in,
                               const float* __restrict__ W,
                               const float* __restrict__ bias,
                               float* __restrict__ out,
                               int K, int apply_gelu) {
    __shared__ float red[4];
    int n = blockIdx.x, b = blockIdx.y, t = threadIdx.x;  // 128 threads
    int N = gridDim.x;
    const float* ip = in + (size_t)b * K;
    const float* wp = W + (size_t)n * K;
    float s = 0.f;
    for (int k = t; k < K; k += 128) s += ip[k] * wp[k];
    #pragma unroll
    for (int o = 16; o > 0; o >>= 1) s += __shfl_down_sync(0xffffffffu, s, o);
    if ((t & 31) == 0) red[t >> 5] = s;
    __syncthreads();
    if (t == 0) {
        float v = red[0] + red[1] + red[2] + red[3] + bias[n];
        if (apply_gelu) v = gelu_exact(v);
        out[b * N + n] = v;
    }
}

// ---------------- launch ----------------
extern "C" void kernel_launch(void* const* d_in, const int* in_sizes, int n_in,
                              void* d_out, int out_size) {
    const int*   x_ids  = (const int*)d_in[0];
    const int*   mask   = (const int*)d_in[1];
    const float* emb    = (const float*)d_in[2];
    const float* qkv_w  = (const float*)d_in[3];
    const float* fc_w   = (const float*)d_in[4];
    const float* fc_b   = (const float*)d_in[5];
    const float* ln1_g  = (const float*)d_in[6];
    const float* ln1_b  = (const float*)d_in[7];
    const float* ffn_w1 = (const float*)d_in[8];
    const float* ffn_b1 = (const float*)d_in[9];
    const float* ffn_w2 = (const float*)d_in[10];
    const float* ffn_b2 = (const float*)d_in[11];
    const float* ln2_g  = (const float*)d_in[12];
    const float* ln2_b  = (const float*)d_in[13];
    const float* pr_w1  = (const float*)d_in[14];
    const float* pr_b1  = (const float*)d_in[15];
    const float* pr_w2  = (const float*)d_in[16];
    const float* pr_b2  = (const float*)d_in[17];
    float* out = (float*)d_out;

    float *X, *QKV, *AO, *O, *Hb, *part, *pool, *hh;
    cudaGetSymbolAddress((void**)&X,    g_X);
    cudaGetSymbolAddress((void**)&QKV,  g_QKV);
    cudaGetSymbolAddress((void**)&AO,   g_AO);
    cudaGetSymbolAddress((void**)&O,    g_O);
    cudaGetSymbolAddress((void**)&Hb,   g_H);
    cudaGetSymbolAddress((void**)&part, g_part);
    cudaGetSymbolAddress((void**)&pool, g_pool);
    cudaGetSymbolAddress((void**)&hh,   g_hh);

    // 1. embedding + positional encoding
    embed_pe_kernel<<<(NTOK * (DD / 2)) / 256, 256>>>(x_ids, emb, X);

    // 2. QKV projection: [8192,1024] x [3072,1024]^T
    gemm_tc_kernel<0><<<dim3(3 * DD / 128, NTOK / 128), 256>>>(
        X, qkv_w, nullptr, QKV, NTOK, 3 * DD, DD);

    // 3. attention (tf32 tensor cores)
    flash_tc_kernel<<<dim3(SS / 64, HH, BB), 128>>>(QKV, mask, AO);

    // 4. output projection (+bias)
    gemm_tc_kernel<1><<<dim3(DD / 128, NTOK / 128), 256>>>(
        AO, fc_w, fc_b, O, NTOK, DD, DD);

    // 5. residual + LN1 (in-place into X)
    add_ln_kernel<<<NTOK, 256>>>(O, X, ln1_g, ln1_b);

    // 6. FFN up (+bias, gelu)
    gemm_tc_kernel<2><<<dim3(FFN / 128, NTOK / 128), 256>>>(
        X, ffn_w1, ffn_b1, Hb, NTOK, FFN, DD);

    // 7. FFN down (+bias)
    gemm_tc_kernel<1><<<dim3(DD / 128, NTOK / 128), 256>>>(
        Hb, ffn_w2, ffn_b2, O, NTOK, DD, FFN);

    // 8. residual + LN2
    add_ln_kernel<<<NTOK, 256>>>(O, X, ln2_g, ln2_b);

    // 9. masked max-pool
    pool_partial_kernel<<<dim3(16, BB), 1024>>>(X, mask, part);
    pool_final_kernel<<<BB, 1024>>>(part, pool);

    // 10. prediction head
    head_fc_kernel<<<dim3(DD, BB), 128>>>(pool, pr_w1, pr_b1, hh, DD, 1);
    head_fc_kernel<<<dim3(10, BB), 128>>>(hh, pr_w2, pr_b2, out, DD, 0);
}

// round 4
// speedup vs baseline: 4.8420x; 1.2149x over previous
#include <cuda_runtime.h>
#include <cuda_bf16.h>
#include <math.h>
#include <stdint.h>

// Problem constants
#define BB 4
#define SS 2048
#define DD 1024
#define HH 16
#define HDIM 64
#define FFN 2048
#define NTOK (BB*SS)          // 8192

// ---------------- scratch (device globals: allocation-free) ----------------
__device__ float g_X   [NTOK * DD];
__device__ float g_QKV [NTOK * 3 * DD];
__device__ float g_AO  [NTOK * DD];
__device__ float g_O   [NTOK * DD];
__device__ float g_H   [NTOK * FFN];
__device__ float g_part[BB * 16 * DD];
__device__ float g_pool[BB * DD];
__device__ float g_hh  [BB * DD];

__device__ __forceinline__ float gelu_exact(float v) {
    return 0.5f * v * (1.0f + erff(v * 0.7071067811865476f));
}

__device__ __forceinline__ uint32_t smem_u32(const void* p) {
    return (uint32_t)__cvta_generic_to_shared(p);
}
__device__ __forceinline__ void cp16(uint32_t dst, const void* src) {
    asm volatile("cp.async.cg.shared.global [%0], [%1], 16;" :: "r"(dst), "l"(src));
}
__device__ __forceinline__ void cp_commit() {
    asm volatile("cp.async.commit_group;");
}
template<int N>
__device__ __forceinline__ void cp_wait() {
    asm volatile("cp.async.wait_group %0;" :: "n"(N));
}

__device__ __forceinline__ void mma_tf32(float* d, const uint32_t* a, uint32_t b0, uint32_t b1) {
    asm volatile(
        "mma.sync.aligned.m16n8k8.row.col.f32.tf32.tf32.f32 "
        "{%0,%1,%2,%3}, {%4,%5,%6,%7}, {%8,%9}, {%0,%1,%2,%3};\n"
        : "+f"(d[0]), "+f"(d[1]), "+f"(d[2]), "+f"(d[3])
        : "r"(a[0]), "r"(a[1]), "r"(a[2]), "r"(a[3]), "r"(b0), "r"(b1));
}

// ---------------- embedding + positional encoding ----------------
__global__ void embed_pe_kernel(const int* __restrict__ ids,
                                const float* __restrict__ emb,
                                float* __restrict__ X) {
    int idx = blockIdx.x * blockDim.x + threadIdx.x;
    if (idx >= NTOK * (DD / 2)) return;
    int row = idx >> 9;
    int p   = idx & 511;
    int s   = row & (SS - 1);
    int id  = ids[row];
    float freq = expf(-0.017988946039015358f * (float)p);  // 2*ln(1e4)/1024
    float sv, cv;
    sincosf((float)s * freq, &sv, &cv);
    size_t eo = (size_t)id * DD + 2 * p;
    size_t xo = (size_t)row * DD + 2 * p;
    X[xo]     = emb[eo]     + sv;
    X[xo + 1] = emb[eo + 1] + cv;
}

// ---------------- tf32 tensor-core GEMM, cp.async double-buffered ---------
// C = A(MxK) * W(NxK)^T. BM=BN=128, BK=16, 256 threads, warp tile 64x32.
template<int EPI>   // 0 = none, 1 = +bias, 2 = gelu(+bias)
__launch_bounds__(256, 2)
__global__ void gemm_tc_kernel(const float* __restrict__ A,
                               const float* __restrict__ W,
                               const float* __restrict__ bias,
                               float* __restrict__ C,
                               int M, int N, int K) {
    __shared__ __align__(16) float As[2][128][20];
    __shared__ __align__(16) float Ws[2][128][20];

    const int tid  = threadIdx.x;
    const int lane = tid & 31, warp = tid >> 5;
    const int wm = warp >> 2, wn = warp & 3;
    const int wrow = wm * 64, wcol = wn * 32;
    const int m0 = blockIdx.y * 128, n0 = blockIdx.x * 128;
    const int g = lane >> 2, tg = lane & 3;
    const int lr = tid >> 2, lc = (tid & 3) * 4;

    auto issue = [&](int st, int k0) {
        #pragma unroll
        for (int i = 0; i < 2; i++) {
            int r = lr + 64 * i;
            cp16(smem_u32(&As[st][r][lc]), A + (size_t)(m0 + r) * K + k0 + lc);
            cp16(smem_u32(&Ws[st][r][lc]), W + (size_t)(n0 + r) * K + k0 + lc);
        }
    };

    float acc[4][4][4];
    #pragma unroll
    for (int mt = 0; mt < 4; mt++)
        #pragma unroll
        for (int nt = 0; nt < 4; nt++)
            #pragma unroll
            for (int r = 0; r < 4; r++) acc[mt][nt][r] = 0.f;

    issue(0, 0);
    cp_commit();
    const int nIter = K / 16;

    for (int it = 0; it < nIter; it++) {
        if (it + 1 < nIter) issue((it + 1) & 1, (it + 1) * 16);
        cp_commit();
        cp_wait<1>();
        __syncthreads();
        const int st = it & 1;

        #pragma unroll
        for (int ks = 0; ks < 2; ks++) {
            int kk = ks * 8;
            uint32_t af[4][4], bf[4][2];
            #pragma unroll
            for (int mt = 0; mt < 4; mt++) {
                int r = wrow + mt * 16 + g;
                af[mt][0] = __float_as_uint(As[st][r][kk + tg]);
                af[mt][1] = __float_as_uint(As[st][r + 8][kk + tg]);
                af[mt][2] = __float_as_uint(As[st][r][kk + tg + 4]);
                af[mt][3] = __float_as_uint(As[st][r + 8][kk + tg + 4]);
            }
            #pragma unroll
            for (int nt = 0; nt < 4; nt++) {
                int r = wcol + nt * 8 + g;
                bf[nt][0] = __float_as_uint(Ws[st][r][kk + tg]);
                bf[nt][1] = __float_as_uint(Ws[st][r][kk + tg + 4]);
            }
            #pragma unroll
            for (int mt = 0; mt < 4; mt++)
                #pragma unroll
                for (int nt = 0; nt < 4; nt++)
                    mma_tf32(acc[mt][nt], af[mt], bf[nt][0], bf[nt][1]);
        }
        __syncthreads();
    }

    // epilogue
    #pragma unroll
    for (int mt = 0; mt < 4; mt++) {
        int r0 = m0 + wrow + mt * 16 + g;
        #pragma unroll
        for (int nt = 0; nt < 4; nt++) {
            int c = n0 + wcol + nt * 8 + 2 * tg;
            float b0 = 0.f, b1 = 0.f;
            if (EPI >= 1) { b0 = bias[c]; b1 = bias[c + 1]; }
            float v00 = acc[mt][nt][0] + b0, v01 = acc[mt][nt][1] + b1;
            float v10 = acc[mt][nt][2] + b0, v11 = acc[mt][nt][3] + b1;
            if (EPI == 2) {
                v00 = gelu_exact(v00); v01 = gelu_exact(v01);
                v10 = gelu_exact(v10); v11 = gelu_exact(v11);
            }
            *reinterpret_cast<float2*>(C + (size_t)r0 * N + c)       = make_float2(v00, v01);
            *reinterpret_cast<float2*>(C + (size_t)(r0 + 8) * N + c) = make_float2(v10, v11);
        }
    }
}

// ---------------- tf32 flash attention, cp.async double-buffered ----------
// grid (S/64, H, B), 128 threads (4 warps). 64-query tile, 32-key chunks.
// Q is staged through the Ks double-buffer region, then lives in registers.
__launch_bounds__(128, 4)
__global__ void flash_tc_kernel(const float* __restrict__ qkv,
                                const int* __restrict__ mask,
                                float* __restrict__ out) {
    __shared__ __align__(16) float Ks[2][32][68];   // also Q staging [64][68]
    __shared__ __align__(16) float Vs[2][32][72];
    __shared__ float Ps[64][36];
    __shared__ __align__(16) int msk[2][32];

    const int b = blockIdx.z, h = blockIdx.y;
    const int q0 = blockIdx.x * 64;
    const int tid = threadIdx.x, lane = tid & 31, warp = tid >> 5;
    const int g = lane >> 2, tg = lane & 3;
    const size_t base = (size_t)b * SS;
    const int qcol = h * HDIM;

    // stage Q (scaled by 1/sqrt(HD)=0.125) into Ks region viewed as [64][68]
    float* qst = &Ks[0][0][0];
    #pragma unroll
    for (int i = 0; i < 8; i++) {
        int idx = tid + 128 * i;
        int r = idx >> 4, c = (idx & 15) * 4;
        float4 v = *reinterpret_cast<const float4*>(
            qkv + (base + q0 + r) * (3 * DD) + qcol + c);
        qst[r * 68 + c]     = v.x * 0.125f;
        qst[r * 68 + c + 1] = v.y * 0.125f;
        qst[r * 68 + c + 2] = v.z * 0.125f;
        qst[r * 68 + c + 3] = v.w * 0.125f;
    }
    __syncthreads();

    uint32_t qf[8][4];
    #pragma unroll
    for (int ks = 0; ks < 8; ks++) {
        int r = warp * 16 + g, c = ks * 8 + tg;
        qf[ks][0] = __float_as_uint(qst[r * 68 + c]);
        qf[ks][1] = __float_as_uint(qst[(r + 8) * 68 + c]);
        qf[ks][2] = __float_as_uint(qst[r * 68 + c + 4]);
        qf[ks][3] = __float_as_uint(qst[(r + 8) * 68 + c + 4]);
    }
    __syncthreads();   // Q reads done before K pipeline overwrites region

    auto issueKV = [&](int st, int kc) {
        #pragma unroll
        for (int i = 0; i < 4; i++) {
            int idx = tid + 128 * i;
            int r = idx >> 4, c = (idx & 15) * 4;
            const float* src = qkv + (base + kc + r) * (3 * DD) + qcol;
            cp16(smem_u32(&Ks[st][r][c]), src + DD + c);
            cp16(smem_u32(&Vs[st][r][c]), src + 2 * DD + c);
        }
        if (tid < 8) cp16(smem_u32(&msk[st][tid * 4]), mask + b * SS + kc + tid * 4);
    };

    float o[8][4];
    #pragma unroll
    for (int nt = 0; nt < 8; nt++)
        #pragma unroll
        for (int r = 0; r < 4; r++) o[nt][r] = 0.f;
    float mprev0 = -1e30f, mprev1 = -1e30f;
    float l0 = 0.f, l1 = 0.f;

    issueKV(0, 0);
    cp_commit();

    for (int it = 0; it < SS / 32; it++) {
        if (it + 1 < SS / 32) issueKV((it + 1) & 1, (it + 1) * 32);
        cp_commit();
        cp_wait<1>();
        __syncthreads();
        const int st = it & 1;

        // S = Q K^T
        float s[4][4];
        #pragma unroll
        for (int nt = 0; nt < 4; nt++)
            #pragma unroll
            for (int r = 0; r < 4; r++) s[nt][r] = 0.f;
        #pragma unroll
        for (int ks = 0; ks < 8; ks++) {
            #pragma unroll
            for (int nt = 0; nt < 4; nt++) {
                uint32_t b0 = __float_as_uint(Ks[st][nt * 8 + g][ks * 8 + tg]);
                uint32_t b1 = __float_as_uint(Ks[st][nt * 8 + g][ks * 8 + tg + 4]);
                mma_tf32(s[nt], qf[ks], b0, b1);
            }
        }

        // mask + row max
        float mx0 = -1e30f, mx1 = -1e30f;
        #pragma unroll
        for (int nt = 0; nt < 4; nt++) {
            int c = nt * 8 + 2 * tg;
            if (msk[st][c] == 0)     { s[nt][0] = -1e30f; s[nt][2] = -1e30f; }
            if (msk[st][c + 1] == 0) { s[nt][1] = -1e30f; s[nt][3] = -1e30f; }
            mx0 = fmaxf(mx0, fmaxf(s[nt][0], s[nt][1]));
            mx1 = fmaxf(mx1, fmaxf(s[nt][2], s[nt][3]));
        }
        mx0 = fmaxf(mx0, __shfl_xor_sync(0xffffffffu, mx0, 1));
        mx0 = fmaxf(mx0, __shfl_xor_sync(0xffffffffu, mx0, 2));
        mx1 = fmaxf(mx1, __shfl_xor_sync(0xffffffffu, mx1, 1));
        mx1 = fmaxf(mx1, __shfl_xor_sync(0xffffffffu, mx1, 2));

        float mn0 = fmaxf(mprev0, mx0), mn1 = fmaxf(mprev1, mx1);
        float a0 = __expf(mprev0 - mn0), a1 = __expf(mprev1 - mn1);

        float ps0 = 0.f, ps1 = 0.f;
        #pragma unroll
        for (int nt = 0; nt < 4; nt++) {
            s[nt][0] = __expf(s[nt][0] - mn0);
            s[nt][1] = __expf(s[nt][1] - mn0);
            s[nt][2] = __expf(s[nt][2] - mn1);
            s[nt][3] = __expf(s[nt][3] - mn1);
            ps0 += s[nt][0] + s[nt][1];
            ps1 += s[nt][2] + s[nt][3];
            int r = warp * 16 + g, c = nt * 8 + 2 * tg;
            Ps[r][c]     = s[nt][0];
            Ps[r][c + 1] = s[nt][1];
            Ps[r + 8][c]     = s[nt][2];
            Ps[r + 8][c + 1] = s[nt][3];
        }
        l0 = l0 * a0 + ps0;
        l1 = l1 * a1 + ps1;
        mprev0 = mn0; mprev1 = mn1;
        __syncwarp();   // P writes visible before frag reads (warp-local rows)

        // O = O*alpha + P V
        #pragma unroll
        for (int nt = 0; nt < 8; nt++) {
            o[nt][0] *= a0; o[nt][1] *= a0;
            o[nt][2] *= a1; o[nt][3] *= a1;
        }
        #pragma unroll
        for (int ks = 0; ks < 4; ks++) {
            uint32_t af[4];
            int r = warp * 16 + g, c = ks * 8 + tg;
            af[0] = __float_as_uint(Ps[r][c]);
            af[1] = __float_as_uint(Ps[r + 8][c]);
            af[2] = __float_as_uint(Ps[r][c + 4]);
            af[3] = __float_as_uint(Ps[r + 8][c + 4]);
            #pragma unroll
            for (int nt = 0; nt < 8; nt++) {
                uint32_t b0 = __float_as_uint(Vs[st][ks * 8 + tg][nt * 8 + g]);
                uint32_t b1 = __float_as_uint(Vs[st][ks * 8 + tg + 4][nt * 8 + g]);
                mma_tf32(o[nt], af, b0, b1);
            }
        }
        __syncthreads();   // stage reads done before it+1's issue overwrites
    }

    l0 += __shfl_xor_sync(0xffffffffu, l0, 1);
    l0 += __shfl_xor_sync(0xffffffffu, l0, 2);
    l1 += __shfl_xor_sync(0xffffffffu, l1, 1);
    l1 += __shfl_xor_sync(0xffffffffu, l1, 2);
    float inv0 = 1.0f / l0, inv1 = 1.0f / l1;

    int r0 = q0 + warp * 16 + g;
    #pragma unroll
    for (int nt = 0; nt < 8; nt++) {
        int c = qcol + nt * 8 + 2 * tg;
        *reinterpret_cast<float2*>(out + (base + r0) * DD + c) =
            make_float2(o[nt][0] * inv0, o[nt][1] * inv0);
        *reinterpret_cast<float2*>(out + (base + r0 + 8) * DD + c) =
            make_float2(o[nt][2] * inv1, o[nt][3] * inv1);
    }
}

// ---------------- residual add + LayerNorm (in-place into X) --------------
__device__ __forceinline__ float block_reduce_256(float v, float* red) {
    __syncthreads();
    int t = threadIdx.x;
    #pragma unroll
    for (int o = 16; o > 0; o >>= 1) v += __shfl_down_sync(0xffffffffu, v, o);
    if ((t & 31) == 0) red[t >> 5] = v;
    __syncthreads();
    if (t < 8) {
        v = red[t];
        #pragma unroll
        for (int o = 4; o > 0; o >>= 1) v += __shfl_down_sync(0xffu, v, o);
        if (t == 0) red[0] = v;
    }
    __syncthreads();
    return red[0];
}

__global__ void add_ln_kernel(const float* __restrict__ A,
                              float* __restrict__ X,
                              const float* __restrict__ g,
                              const float* __restrict__ bt) {
    __shared__ float red[32];
    int r = blockIdx.x, t = threadIdx.x;
    const float* a = A + (size_t)r * DD;
    float* x = X + (size_t)r * DD;
    float v[4];
    float sum = 0.f;
    #pragma unroll
    for (int i = 0; i < 4; i++) {
        int d = t + 256 * i;
        v[i] = a[d] + x[d];
        sum += v[i];
    }
    sum = block_reduce_256(sum, red);
    float mu = sum * (1.0f / DD);
    float vs = 0.f;
    #pragma unroll
    for (int i = 0; i < 4; i++) {
        float dl = v[i] - mu;
        vs += dl * dl;
    }
    vs = block_reduce_256(vs, red);
    float rs = rsqrtf(vs * (1.0f / DD) + 1e-5f);
    #pragma unroll
    for (int i = 0; i < 4; i++) {
        int d = t + 256 * i;
        x[d] = (v[i] - mu) * rs * g[d] + bt[d];
    }
}

// ---------------- masked max-pool over sequence ----------------
__global__ void pool_partial_kernel(const float* __restrict__ X,
                                    const int* __restrict__ mask,
                                    float* __restrict__ part) {
    int b = blockIdx.y, ch = blockIdx.x;
    int d = threadIdx.x;
    float m = -INFINITY;
    for (int s = 0; s < 128; s++) {
        int srow = ch * 128 + s;
        float val = X[((size_t)b * SS + srow) * DD + d];
        if (mask[b * SS + srow] != 0) m = fmaxf(m, val);
    }
    part[((size_t)b * 16 + ch) * DD + d] = m;
}

__global__ void pool_final_kernel(const float* __restrict__ part,
                                  float* __restrict__ pooled) {
    int b = blockIdx.x, d = threadIdx.x;
    float m = -INFINITY;
    for (int c = 0; c < 16; c++)
        m = fmaxf(m, part[((size_t)b * 16 + c) * DD + d]);
    pooled[b * DD + d] = m;
}

// ---------------- small head FC ----------------
__global__ void head_fc_kernel(const float* __restrict__ in,
                               const float* __restrict__ W,
                               const float* __restrict__ bias,
                               float* __restrict__ out,
                               int K, int apply_gelu) {
    __shared__ float red[4];
    int n = blockIdx.x, b = blockIdx.y, t = threadIdx.x;
    int N = gridDim.x;
    const float* ip = in + (size_t)b * K;
    const float* wp = W + (size_t)n * K;
    float s = 0.f;
    for (int k = t; k < K; k += 128) s += ip[k] * wp[k];
    #pragma unroll
    for (int o = 16; o > 0; o >>= 1) s += __shfl_down_sync(0xffffffffu, s, o);
    if ((t & 31) == 0) red[t >> 5] = s;
    __syncthreads();
    if (t == 0) {
        float v = red[0] + red[1] + red[2] + red[3] + bias[n];
        if (apply_gelu) v = gelu_exact(v);
        out[b * N + n] = v;
    }
}

// ---------------- launch ----------------
extern "C" void kernel_launch(void* const* d_in, const int* in_sizes, int n_in,
                              void* d_out, int out_size) {
    const int*   x_ids  = (const int*)d_in[0];
    const int*   mask   = (const int*)d_in[1];
    const float* emb    = (const float*)d_in[2];
    const float* qkv_w  = (const float*)d_in[3];
    const float* fc_w   = (const float*)d_in[4];
    const float* fc_b   = (const float*)d_in[5];
    const float* ln1_g  = (const float*)d_in[6];
    const float* ln1_b  = (const float*)d_in[7];
    const float* ffn_w1 = (const float*)d_in[8];
    const float* ffn_b1 = (const float*)d_in[9];
    const float* ffn_w2 = (const float*)d_in[10];
    const float* ffn_b2 = (const float*)d_in[11];
    const float* ln2_g  = (const float*)d_in[12];
    const float* ln2_b  = (const float*)d_in[13];
    const float* pr_w1  = (const float*)d_in[14];
    const float* pr_b1  = (const float*)d_in[15];
    const float* pr_w2  = (const float*)d_in[16];
    const float* pr_b2  = (const float*)d_in[17];
    float* out = (float*)d_out;

    float *X, *QKV, *AO, *O, *Hb, *part, *pool, *hh;
    cudaGetSymbolAddress((void**)&X,    g_X);
    cudaGetSymbolAddress((void**)&QKV,  g_QKV);
    cudaGetSymbolAddress((void**)&AO,   g_AO);
    cudaGetSymbolAddress((void**)&O,    g_O);
    cudaGetSymbolAddress((void**)&Hb,   g_H);
    cudaGetSymbolAddress((void**)&part, g_part);
    cudaGetSymbolAddress((void**)&pool, g_pool);
    cudaGetSymbolAddress((void**)&hh,   g_hh);

    // 1. embedding + positional encoding
    embed_pe_kernel<<<(NTOK * (DD / 2)) / 256, 256>>>(x_ids, emb, X);

    // 2. QKV projection
    gemm_tc_kernel<0><<<dim3(3 * DD / 128, NTOK / 128), 256>>>(
        X, qkv_w, nullptr, QKV, NTOK, 3 * DD, DD);

    // 3. attention
    flash_tc_kernel<<<dim3(SS / 64, HH, BB), 128>>>(QKV, mask, AO);

    // 4. output projection (+bias)
    gemm_tc_kernel<1><<<dim3(DD / 128, NTOK / 128), 256>>>(
        AO, fc_w, fc_b, O, NTOK, DD, DD);

    // 5. residual + LN1
    add_ln_kernel<<<NTOK, 256>>>(O, X, ln1_g, ln1_b);

    // 6. FFN up (+bias, gelu)
    gemm_tc_kernel<2><<<dim3(FFN / 128, NTOK / 128), 256>>>(
        X, ffn_w1, ffn_b1, Hb, NTOK, FFN, DD);

    // 7. FFN down (+bias)
    gemm_tc_kernel<1><<<dim3(DD / 128, NTOK / 128), 256>>>(
        Hb, ffn_w2, ffn_b2, O, NTOK, DD, FFN);

    // 8. residual + LN2
    add_ln_kernel<<<NTOK, 256>>>(O, X, ln2_g, ln2_b);

    // 9. masked max-pool
    pool_partial_kernel<<<dim3(16, BB), 1024>>>(X, mask, part);
    pool_final_kernel<<<BB, 1024>>>(part, pool);

    // 10. prediction head
    head_fc_kernel<<<dim3(DD, BB), 128>>>(pool, pr_w1, pr_b1, hh, DD, 1);
    head_fc_kernel<<<dim3(10, BB), 128>>>(hh, pr_w2, pr_b2, out, DD, 0);
}

// round 5
// speedup vs baseline: 4.8751x; 1.0068x over previous
#include <cuda_runtime.h>
#include <cuda_bf16.h>
#include <math.h>
#include <stdint.h>

// Problem constants
#define BB 4
#define SS 2048
#define DD 1024
#define HH 16
#define HDIM 64
#define FFN 2048
#define NTOK (BB*SS)          // 8192

// ---------------- scratch (device globals: allocation-free) ----------------
__device__ float g_X   [NTOK * DD];
__device__ float g_QKV [NTOK * 3 * DD];
__device__ float g_AO  [NTOK * DD];
__device__ float g_O   [NTOK * DD];
__device__ float g_H   [NTOK * FFN];
__device__ float g_part[BB * 16 * DD];
__device__ float g_pool[BB * DD];
__device__ float g_hh  [BB * DD];

__device__ __forceinline__ float gelu_exact(float v) {
    return 0.5f * v * (1.0f + erff(v * 0.7071067811865476f));
}

__device__ __forceinline__ uint32_t smem_u32(const void* p) {
    return (uint32_t)__cvta_generic_to_shared(p);
}
__device__ __forceinline__ void cp16(uint32_t dst, const void* src) {
    asm volatile("cp.async.cg.shared.global [%0], [%1], 16;" :: "r"(dst), "l"(src));
}
__device__ __forceinline__ void cp_commit() {
    asm volatile("cp.async.commit_group;");
}
template<int N>
__device__ __forceinline__ void cp_wait() {
    asm volatile("cp.async.wait_group %0;" :: "n"(N));
}

__device__ __forceinline__ void mma_tf32(float* d, const uint32_t* a, uint32_t b0, uint32_t b1) {
    asm volatile(
        "mma.sync.aligned.m16n8k8.row.col.f32.tf32.tf32.f32 "
        "{%0,%1,%2,%3}, {%4,%5,%6,%7}, {%8,%9}, {%0,%1,%2,%3};\n"
        : "+f"(d[0]), "+f"(d[1]), "+f"(d[2]), "+f"(d[3])
        : "r"(a[0]), "r"(a[1]), "r"(a[2]), "r"(a[3]), "r"(b0), "r"(b1));
}

// ---------------- embedding + positional encoding ----------------
__global__ void embed_pe_kernel(const int* __restrict__ ids,
                                const float* __restrict__ emb,
                                float* __restrict__ X) {
    int idx = blockIdx.x * blockDim.x + threadIdx.x;
    if (idx >= NTOK * (DD / 2)) return;
    int row = idx >> 9;
    int p   = idx & 511;
    int s   = row & (SS - 1);
    int id  = ids[row];
    float freq = expf(-0.017988946039015358f * (float)p);  // 2*ln(1e4)/1024
    float sv, cv;
    sincosf((float)s * freq, &sv, &cv);
    size_t eo = (size_t)id * DD + 2 * p;
    size_t xo = (size_t)row * DD + 2 * p;
    X[xo]     = emb[eo]     + sv;
    X[xo + 1] = emb[eo + 1] + cv;
}

// ---------------- tf32 tensor-core GEMM, 3-stage cp.async pipeline --------
// C = A(MxK) * W(NxK)^T. BM=BN=128, BK=16, 256 threads, warp tile 64x32.
// One __syncthreads per K-step; wait_group<1> gives ~2 iterations of latency cover.
template<int EPI>   // 0 = none, 1 = +bias, 2 = gelu(+bias)
__launch_bounds__(256, 2)
__global__ void gemm_tc_kernel(const float* __restrict__ A,
                               const float* __restrict__ W,
                               const float* __restrict__ bias,
                               float* __restrict__ C,
                               int M, int N, int K) {
    __shared__ __align__(16) float As[3][128][20];
    __shared__ __align__(16) float Ws[3][128][20];

    const int tid  = threadIdx.x;
    const int lane = tid & 31, warp = tid >> 5;
    const int wm = warp >> 2, wn = warp & 3;
    const int wrow = wm * 64, wcol = wn * 32;
    const int m0 = blockIdx.y * 128, n0 = blockIdx.x * 128;
    const int g = lane >> 2, tg = lane & 3;
    const int lr = tid >> 2, lc = (tid & 3) * 4;

    auto issue = [&](int st, int k0) {
        #pragma unroll
        for (int i = 0; i < 2; i++) {
            int r = lr + 64 * i;
            cp16(smem_u32(&As[st][r][lc]), A + (size_t)(m0 + r) * K + k0 + lc);
            cp16(smem_u32(&Ws[st][r][lc]), W + (size_t)(n0 + r) * K + k0 + lc);
        }
    };

    float acc[4][4][4];
    #pragma unroll
    for (int mt = 0; mt < 4; mt++)
        #pragma unroll
        for (int nt = 0; nt < 4; nt++)
            #pragma unroll
            for (int r = 0; r < 4; r++) acc[mt][nt][r] = 0.f;

    const int nIter = K / 16;
    issue(0, 0);  cp_commit();
    issue(1, 16); cp_commit();

    for (int it = 0; it < nIter; it++) {
        if (it == nIter - 1) cp_wait<0>(); else cp_wait<1>();
        __syncthreads();
        if (it + 2 < nIter) { issue((it + 2) % 3, (it + 2) * 16); cp_commit(); }
        const int st = it % 3;

        #pragma unroll
        for (int ks = 0; ks < 2; ks++) {
            int kk = ks * 8;
            uint32_t af[4][4], bf[4][2];
            #pragma unroll
            for (int mt = 0; mt < 4; mt++) {
                int r = wrow + mt * 16 + g;
                af[mt][0] = __float_as_uint(As[st][r][kk + tg]);
                af[mt][1] = __float_as_uint(As[st][r + 8][kk + tg]);
                af[mt][2] = __float_as_uint(As[st][r][kk + tg + 4]);
                af[mt][3] = __float_as_uint(As[st][r + 8][kk + tg + 4]);
            }
            #pragma unroll
            for (int nt = 0; nt < 4; nt++) {
                int r = wcol + nt * 8 + g;
                bf[nt][0] = __float_as_uint(Ws[st][r][kk + tg]);
                bf[nt][1] = __float_as_uint(Ws[st][r][kk + tg + 4]);
            }
            #pragma unroll
            for (int mt = 0; mt < 4; mt++)
                #pragma unroll
                for (int nt = 0; nt < 4; nt++)
                    mma_tf32(acc[mt][nt], af[mt], bf[nt][0], bf[nt][1]);
        }
    }

    // epilogue
    #pragma unroll
    for (int mt = 0; mt < 4; mt++) {
        int r0 = m0 + wrow + mt * 16 + g;
        #pragma unroll
        for (int nt = 0; nt < 4; nt++) {
            int c = n0 + wcol + nt * 8 + 2 * tg;
            float b0 = 0.f, b1 = 0.f;
            if (EPI >= 1) { b0 = bias[c]; b1 = bias[c + 1]; }
            float v00 = acc[mt][nt][0] + b0, v01 = acc[mt][nt][1] + b1;
            float v10 = acc[mt][nt][2] + b0, v11 = acc[mt][nt][3] + b1;
            if (EPI == 2) {
                v00 = gelu_exact(v00); v01 = gelu_exact(v01);
                v10 = gelu_exact(v10); v11 = gelu_exact(v11);
            }
            *reinterpret_cast<float2*>(C + (size_t)r0 * N + c)       = make_float2(v00, v01);
            *reinterpret_cast<float2*>(C + (size_t)(r0 + 8) * N + c) = make_float2(v10, v11);
        }
    }
}

// ---------------- tf32 flash attention, 3-stage cp.async pipeline ---------
// grid (S/64, H, B), 128 threads (4 warps). 64-query tile, 32-key chunks.
// One __syncthreads per chunk; P stays warp-local (syncwarp only).
__launch_bounds__(128, 3)
__global__ void flash_tc_kernel(const float* __restrict__ qkv,
                                const int* __restrict__ mask,
                                float* __restrict__ out) {
    __shared__ __align__(16) float Ks[3][32][68];   // stages 0..1 double as Q staging [64][68]
    __shared__ __align__(16) float Vs[3][32][72];
    __shared__ float Ps[64][36];
    __shared__ __align__(16) int msk[3][32];

    const int b = blockIdx.z, h = blockIdx.y;
    const int q0 = blockIdx.x * 64;
    const int tid = threadIdx.x, lane = tid & 31, warp = tid >> 5;
    const int g = lane >> 2, tg = lane & 3;
    const size_t base = (size_t)b * SS;
    const int qcol = h * HDIM;

    // stage Q (scaled by 1/sqrt(HD)=0.125) into Ks[0..1] viewed as [64][68]
    float* qst = &Ks[0][0][0];
    #pragma unroll
    for (int i = 0; i < 8; i++) {
        int idx = tid + 128 * i;
        int r = idx >> 4, c = (idx & 15) * 4;
        float4 v = *reinterpret_cast<const float4*>(
            qkv + (base + q0 + r) * (3 * DD) + qcol + c);
        qst[r * 68 + c]     = v.x * 0.125f;
        qst[r * 68 + c + 1] = v.y * 0.125f;
        qst[r * 68 + c + 2] = v.z * 0.125f;
        qst[r * 68 + c + 3] = v.w * 0.125f;
    }
    __syncthreads();

    uint32_t qf[8][4];
    #pragma unroll
    for (int ks = 0; ks < 8; ks++) {
        int r = warp * 16 + g, c = ks * 8 + tg;
        qf[ks][0] = __float_as_uint(qst[r * 68 + c]);
        qf[ks][1] = __float_as_uint(qst[(r + 8) * 68 + c]);
        qf[ks][2] = __float_as_uint(qst[r * 68 + c + 4]);
        qf[ks][3] = __float_as_uint(qst[(r + 8) * 68 + c + 4]);
    }
    __syncthreads();   // Q reads done before KV pipeline overwrites region

    auto issueKV = [&](int st, int kc) {
        #pragma unroll
        for (int i = 0; i < 4; i++) {
            int idx = tid + 128 * i;
            int r = idx >> 4, c = (idx & 15) * 4;
            const float* src = qkv + (base + kc + r) * (3 * DD) + qcol;
            cp16(smem_u32(&Ks[st][r][c]), src + DD + c);
            cp16(smem_u32(&Vs[st][r][c]), src + 2 * DD + c);
        }
        if (tid < 8) cp16(smem_u32(&msk[st][tid * 4]), mask + b * SS + kc + tid * 4);
    };

    float o[8][4];
    #pragma unroll
    for (int nt = 0; nt < 8; nt++)
        #pragma unroll
        for (int r = 0; r < 4; r++) o[nt][r] = 0.f;
    float mprev0 = -1e30f, mprev1 = -1e30f;
    float l0 = 0.f, l1 = 0.f;

    const int nIter = SS / 32;   // 64
    issueKV(0, 0);  cp_commit();
    issueKV(1, 32); cp_commit();

    for (int it = 0; it < nIter; it++) {
        if (it == nIter - 1) cp_wait<0>(); else cp_wait<1>();
        __syncthreads();
        if (it + 2 < nIter) { issueKV((it + 2) % 3, (it + 2) * 32); cp_commit(); }
        const int st = it % 3;

        // S = Q K^T
        float s[4][4];
        #pragma unroll
        for (int nt = 0; nt < 4; nt++)
            #pragma unroll
            for (int r = 0; r < 4; r++) s[nt][r] = 0.f;
        #pragma unroll
        for (int ks = 0; ks < 8; ks++) {
            #pragma unroll
            for (int nt = 0; nt < 4; nt++) {
                uint32_t b0 = __float_as_uint(Ks[st][nt * 8 + g][ks * 8 + tg]);
                uint32_t b1 = __float_as_uint(Ks[st][nt * 8 + g][ks * 8 + tg + 4]);
                mma_tf32(s[nt], qf[ks], b0, b1);
            }
        }

        // mask + row max
        float mx0 = -1e30f, mx1 = -1e30f;
        #pragma unroll
        for (int nt = 0; nt < 4; nt++) {
            int c = nt * 8 + 2 * tg;
            if (msk[st][c] == 0)     { s[nt][0] = -1e30f; s[nt][2] = -1e30f; }
            if (msk[st][c + 1] == 0) { s[nt][1] = -1e30f; s[nt][3] = -1e30f; }
            mx0 = fmaxf(mx0, fmaxf(s[nt][0], s[nt][1]));
            mx1 = fmaxf(mx1, fmaxf(s[nt][2], s[nt][3]));
        }
        mx0 = fmaxf(mx0, __shfl_xor_sync(0xffffffffu, mx0, 1));
        mx0 = fmaxf(mx0, __shfl_xor_sync(0xffffffffu, mx0, 2));
        mx1 = fmaxf(mx1, __shfl_xor_sync(0xffffffffu, mx1, 1));
        mx1 = fmaxf(mx1, __shfl_xor_sync(0xffffffffu, mx1, 2));

        float mn0 = fmaxf(mprev0, mx0), mn1 = fmaxf(mprev1, mx1);
        float a0 = __expf(mprev0 - mn0), a1 = __expf(mprev1 - mn1);

        float ps0 = 0.f, ps1 = 0.f;
        #pragma unroll
        for (int nt = 0; nt < 4; nt++) {
            s[nt][0] = __expf(s[nt][0] - mn0);
            s[nt][1] = __expf(s[nt][1] - mn0);
            s[nt][2] = __expf(s[nt][2] - mn1);
            s[nt][3] = __expf(s[nt][3] - mn1);
            ps0 += s[nt][0] + s[nt][1];
            ps1 += s[nt][2] + s[nt][3];
            int r = warp * 16 + g, c = nt * 8 + 2 * tg;
            Ps[r][c]     = s[nt][0];
            Ps[r][c + 1] = s[nt][1];
            Ps[r + 8][c]     = s[nt][2];
            Ps[r + 8][c + 1] = s[nt][3];
        }
        l0 = l0 * a0 + ps0;
        l1 = l1 * a1 + ps1;
        mprev0 = mn0; mprev1 = mn1;
        __syncwarp();   // P writes visible before frag reads (warp-local rows)

        // O = O*alpha + P V
        #pragma unroll
        for (int nt = 0; nt < 8; nt++) {
            o[nt][0] *= a0; o[nt][1] *= a0;
            o[nt][2] *= a1; o[nt][3] *= a1;
        }
        #pragma unroll
        for (int ks = 0; ks < 4; ks++) {
            uint32_t af[4];
            int r = warp * 16 + g, c = ks * 8 + tg;
            af[0] = __float_as_uint(Ps[r][c]);
            af[1] = __float_as_uint(Ps[r + 8][c]);
            af[2] = __float_as_uint(Ps[r][c + 4]);
            af[3] = __float_as_uint(Ps[r + 8][c + 4]);
            #pragma unroll
            for (int nt = 0; nt < 8; nt++) {
                uint32_t b0 = __float_as_uint(Vs[st][ks * 8 + tg][nt * 8 + g]);
                uint32_t b1 = __float_as_uint(Vs[st][ks * 8 + tg + 4][nt * 8 + g]);
                mma_tf32(o[nt], af, b0, b1);
            }
        }
        __syncwarp();   // P reads done before next chunk rewrites warp rows
    }

    l0 += __shfl_xor_sync(0xffffffffu, l0, 1);
    l0 += __shfl_xor_sync(0xffffffffu, l0, 2);
    l1 += __shfl_xor_sync(0xffffffffu, l1, 1);
    l1 += __shfl_xor_sync(0xffffffffu, l1, 2);
    float inv0 = 1.0f / l0, inv1 = 1.0f / l1;

    int r0 = q0 + warp * 16 + g;
    #pragma unroll
    for (int nt = 0; nt < 8; nt++) {
        int c = qcol + nt * 8 + 2 * tg;
        *reinterpret_cast<float2*>(out + (base + r0) * DD + c) =
            make_float2(o[nt][0] * inv0, o[nt][1] * inv0);
        *reinterpret_cast<float2*>(out + (base + r0 + 8) * DD + c) =
            make_float2(o[nt][2] * inv1, o[nt][3] * inv1);
    }
}

// ---------------- residual add + LayerNorm (in-place into X) --------------
__device__ __forceinline__ float block_reduce_256(float v, float* red) {
    __syncthreads();
    int t = threadIdx.x;
    #pragma unroll
    for (int o = 16; o > 0; o >>= 1) v += __shfl_down_sync(0xffffffffu, v, o);
    if ((t & 31) == 0) red[t >> 5] = v;
    __syncthreads();
    if (t < 8) {
        v = red[t];
        #pragma unroll
        for (int o = 4; o > 0; o >>= 1) v += __shfl_down_sync(0xffu, v, o);
        if (t == 0) red[0] = v;
    }
    __syncthreads();
    return red[0];
}

__global__ void add_ln_kernel(const float* __restrict__ A,
                              float* __restrict__ X,
                              const float* __restrict__ g,
                              const float* __restrict__ bt) {
    __shared__ float red[32];
    int r = blockIdx.x, t = threadIdx.x;
    const float* a = A + (size_t)r * DD;
    float* x = X + (size_t)r * DD;
    float v[4];
    float sum = 0.f;
    #pragma unroll
    for (int i = 0; i < 4; i++) {
        int d = t + 256 * i;
        v[i] = a[d] + x[d];
        sum += v[i];
    }
    sum = block_reduce_256(sum, red);
    float mu = sum * (1.0f / DD);
    float vs = 0.f;
    #pragma unroll
    for (int i = 0; i < 4; i++) {
        float dl = v[i] - mu;
        vs += dl * dl;
    }
    vs = block_reduce_256(vs, red);
    float rs = rsqrtf(vs * (1.0f / DD) + 1e-5f);
    #pragma unroll
    for (int i = 0; i < 4; i++) {
        int d = t + 256 * i;
        x[d] = (v[i] - mu) * rs * g[d] + bt[d];
    }
}

// ---------------- masked max-pool over sequence ----------------
__global__ void pool_partial_kernel(const float* __restrict__ X,
                                    const int* __restrict__ mask,
                                    float* __restrict__ part) {
    int b = blockIdx.y, ch = blockIdx.x;
    int d = threadIdx.x;
    float m = -INFINITY;
    for (int s = 0; s < 128; s++) {
        int srow = ch * 128 + s;
        float val = X[((size_t)b * SS + srow) * DD + d];
        if (mask[b * SS + srow] != 0) m = fmaxf(m, val);
    }
    part[((size_t)b * 16 + ch) * DD + d] = m;
}

__global__ void pool_final_kernel(const float* __restrict__ part,
                                  float* __restrict__ pooled) {
    int b = blockIdx.x, d = threadIdx.x;
    float m = -INFINITY;
    for (int c = 0; c < 16; c++)
        m = fmaxf(m, part[((size_t)b * 16 + c) * DD + d]);
    pooled[b * DD + d] = m;
}

// ---------------- small head FC ----------------
__global__ void head_fc_kernel(const float* __restrict__ in,
                               const float* __restrict__ W,
                               const float* __restrict__ bias,
                               float* __restrict__ out,
                               int K, int apply_gelu) {
    __shared__ float red[4];
    int n = blockIdx.x, b = blockIdx.y, t = threadIdx.x;
    int N = gridDim.x;
    const float* ip = in + (size_t)b * K;
    const float* wp = W + (size_t)n * K;
    float s = 0.f;
    for (int k = t; k < K; k += 128) s += ip[k] * wp[k];
    #pragma unroll
    for (int o = 16; o > 0; o >>= 1) s += __shfl_down_sync(0xffffffffu, s, o);
    if ((t & 31) == 0) red[t >> 5] = s;
    __syncthreads();
    if (t == 0) {
        float v = red[0] + red[1] + red[2] + red[3] + bias[n];
        if (apply_gelu) v = gelu_exact(v);
        out[b * N + n] = v;
    }
}

// ---------------- launch ----------------
extern "C" void kernel_launch(void* const* d_in, const int* in_sizes, int n_in,
                              void* d_out, int out_size) {
    const int*   x_ids  = (const int*)d_in[0];
    const int*   mask   = (const int*)d_in[1];
    const float* emb    = (const float*)d_in[2];
    const float* qkv_w  = (const float*)d_in[3];
    const float* fc_w   = (const float*)d_in[4];
    const float* fc_b   = (const float*)d_in[5];
    const float* ln1_g  = (const float*)d_in[6];
    const float* ln1_b  = (const float*)d_in[7];
    const float* ffn_w1 = (const float*)d_in[8];
    const float* ffn_b1 = (const float*)d_in[9];
    const float* ffn_w2 = (const float*)d_in[10];
    const float* ffn_b2 = (const float*)d_in[11];
    const float* ln2_g  = (const float*)d_in[12];
    const float* ln2_b  = (const float*)d_in[13];
    const float* pr_w1  = (const float*)d_in[14];
    const float* pr_b1  = (const float*)d_in[15];
    const float* pr_w2  = (const float*)d_in[16];
    const float* pr_b2  = (const float*)d_in[17];
    float* out = (float*)d_out;

    float *X, *QKV, *AO, *O, *Hb, *part, *pool, *hh;
    cudaGetSymbolAddress((void**)&X,    g_X);
    cudaGetSymbolAddress((void**)&QKV,  g_QKV);
    cudaGetSymbolAddress((void**)&AO,   g_AO);
    cudaGetSymbolAddress((void**)&O,    g_O);
    cudaGetSymbolAddress((void**)&Hb,   g_H);
    cudaGetSymbolAddress((void**)&part, g_part);
    cudaGetSymbolAddress((void**)&pool, g_pool);
    cudaGetSymbolAddress((void**)&hh,   g_hh);

    // 1. embedding + positional encoding
    embed_pe_kernel<<<(NTOK * (DD / 2)) / 256, 256>>>(x_ids, emb, X);

    // 2. QKV projection
    gemm_tc_kernel<0><<<dim3(3 * DD / 128, NTOK / 128), 256>>>(
        X, qkv_w, nullptr, QKV, NTOK, 3 * DD, DD);

    // 3. attention
    flash_tc_kernel<<<dim3(SS / 64, HH, BB), 128>>>(QKV, mask, AO);

    // 4. output projection (+bias)
    gemm_tc_kernel<1><<<dim3(DD / 128, NTOK / 128), 256>>>(
        AO, fc_w, fc_b, O, NTOK, DD, DD);

    // 5. residual + LN1
    add_ln_kernel<<<NTOK, 256>>>(O, X, ln1_g, ln1_b);

    // 6. FFN up (+bias, gelu)
    gemm_tc_kernel<2><<<dim3(FFN / 128, NTOK / 128), 256>>>(
        X, ffn_w1, ffn_b1, Hb, NTOK, FFN, DD);

    // 7. FFN down (+bias)
    gemm_tc_kernel<1><<<dim3(DD / 128, NTOK / 128), 256>>>(
        Hb, ffn_w2, ffn_b2, O, NTOK, DD, FFN);

    // 8. residual + LN2
    add_ln_kernel<<<NTOK, 256>>>(O, X, ln2_g, ln2_b);

    // 9. masked max-pool
    pool_partial_kernel<<<dim3(16, BB), 1024>>>(X, mask, part);
    pool_final_kernel<<<BB, 1024>>>(part, pool);

    // 10. prediction head
    head_fc_kernel<<<dim3(DD, BB), 128>>>(pool, pr_w1, pr_b1, hh, DD, 1);
    head_fc_kernel<<<dim3(10, BB), 128>>>(hh, pr_w2, pr_b2, out, DD, 0);
}

// round 7
// speedup vs baseline: 5.1839x; 1.0633x over previous
#include <cuda_runtime.h>
#include <cuda_bf16.h>
#include <math.h>
#include <stdint.h>

// Problem constants
#define BB 4
#define SS 2048
#define DD 1024
#define HH 16
#define HDIM 64
#define FFN 2048
#define NTOK (BB*SS)          // 8192

// ---------------- scratch (device globals: allocation-free) ----------------
__device__ float g_X   [NTOK * DD];
__device__ float g_QKV [NTOK * 3 * DD];
__device__ float g_AO  [NTOK * DD];
__device__ float g_O   [NTOK * DD];
__device__ float g_H   [NTOK * FFN];
__device__ float g_part[BB * 16 * DD];
__device__ float g_pool[BB * DD];
__device__ float g_hh  [BB * DD];

__device__ __forceinline__ float gelu_exact(float v) {
    return 0.5f * v * (1.0f + erff(v * 0.7071067811865476f));
}

__device__ __forceinline__ uint32_t smem_u32(const void* p) {
    return (uint32_t)__cvta_generic_to_shared(p);
}
__device__ __forceinline__ void cp16(uint32_t dst, const void* src) {
    asm volatile("cp.async.cg.shared.global [%0], [%1], 16;" :: "r"(dst), "l"(src));
}
__device__ __forceinline__ void cp_commit() {
    asm volatile("cp.async.commit_group;");
}
template<int N>
__device__ __forceinline__ void cp_wait() {
    asm volatile("cp.async.wait_group %0;" :: "n"(N));
}

__device__ __forceinline__ void mma_tf32(float* d, const uint32_t* a, uint32_t b0, uint32_t b1) {
    asm volatile(
        "mma.sync.aligned.m16n8k8.row.col.f32.tf32.tf32.f32 "
        "{%0,%1,%2,%3}, {%4,%5,%6,%7}, {%8,%9}, {%0,%1,%2,%3};\n"
        : "+f"(d[0]), "+f"(d[1]), "+f"(d[2]), "+f"(d[3])
        : "r"(a[0]), "r"(a[1]), "r"(a[2]), "r"(a[3]), "r"(b0), "r"(b1));
}

// ---------------- embedding + positional encoding ----------------
__global__ void embed_pe_kernel(const int* __restrict__ ids,
                                const float* __restrict__ emb,
                                float* __restrict__ X) {
    int idx = blockIdx.x * blockDim.x + threadIdx.x;
    if (idx >= NTOK * (DD / 2)) return;
    int row = idx >> 9;
    int p   = idx & 511;
    int s   = row & (SS - 1);
    int id  = ids[row];
    float freq = expf(-0.017988946039015358f * (float)p);  // 2*ln(1e4)/1024
    float sv, cv;
    sincosf((float)s * freq, &sv, &cv);
    size_t eo = (size_t)id * DD + 2 * p;
    size_t xo = (size_t)row * DD + 2 * p;
    X[xo]     = emb[eo]     + sv;
    X[xo + 1] = emb[eo + 1] + cv;
}

// ---------------- tf32 tensor-core GEMM, 64x64 warp tiles -----------------
// C = A(MxK) * W(NxK)^T. BM=BN=128, BK=16, 128 threads (4 warps, 2x2),
// warp tile 64x64 -> 1.0 LDS per MMA. 3-stage cp.async pipeline.
template<int EPI>   // 0 = none, 1 = +bias, 2 = gelu(+bias)
__launch_bounds__(128, 2)
__global__ void gemm_tc_kernel(const float* __restrict__ A,
                               const float* __restrict__ W,
                               const float* __restrict__ bias,
                               float* __restrict__ C,
                               int M, int N, int K) {
    __shared__ __align__(16) float As[3][128][20];
    __shared__ __align__(16) float Ws[3][128][20];

    const int tid  = threadIdx.x;
    const int lane = tid & 31, warp = tid >> 5;
    const int wm = warp >> 1, wn = warp & 1;
    const int wrow = wm * 64, wcol = wn * 64;
    const int m0 = blockIdx.y * 128, n0 = blockIdx.x * 128;
    const int g = lane >> 2, tg = lane & 3;

    auto issue = [&](int st, int k0) {
        #pragma unroll
        for (int i = 0; i < 4; i++) {
            int u = tid + 128 * i;            // 0..511
            int r = u >> 2, c = (u & 3) * 4;
            cp16(smem_u32(&As[st][r][c]), A + (size_t)(m0 + r) * K + k0 + c);
            cp16(smem_u32(&Ws[st][r][c]), W + (size_t)(n0 + r) * K + k0 + c);
        }
    };

    float acc[4][8][4];
    #pragma unroll
    for (int mt = 0; mt < 4; mt++)
        #pragma unroll
        for (int nt = 0; nt < 8; nt++)
            #pragma unroll
            for (int r = 0; r < 4; r++) acc[mt][nt][r] = 0.f;

    const int nIter = K / 16;
    issue(0, 0);  cp_commit();
    issue(1, 16); cp_commit();

    for (int it = 0; it < nIter; it++) {
        if (it == nIter - 1) cp_wait<0>(); else cp_wait<1>();
        __syncthreads();
        if (it + 2 < nIter) { issue((it + 2) % 3, (it + 2) * 16); cp_commit(); }
        const int st = it % 3;

        #pragma unroll
        for (int ks = 0; ks < 2; ks++) {
            int kk = ks * 8;
            uint32_t af[4][4], bf[8][2];
            #pragma unroll
            for (int mt = 0; mt < 4; mt++) {
                int r = wrow + mt * 16 + g;
                af[mt][0] = __float_as_uint(As[st][r][kk + tg]);
                af[mt][1] = __float_as_uint(As[st][r + 8][kk + tg]);
                af[mt][2] = __float_as_uint(As[st][r][kk + tg + 4]);
                af[mt][3] = __float_as_uint(As[st][r + 8][kk + tg + 4]);
            }
            #pragma unroll
            for (int nt = 0; nt < 8; nt++) {
                int r = wcol + nt * 8 + g;
                bf[nt][0] = __float_as_uint(Ws[st][r][kk + tg]);
                bf[nt][1] = __float_as_uint(Ws[st][r][kk + tg + 4]);
            }
            #pragma unroll
            for (int mt = 0; mt < 4; mt++)
                #pragma unroll
                for (int nt = 0; nt < 8; nt++)
                    mma_tf32(acc[mt][nt], af[mt], bf[nt][0], bf[nt][1]);
        }
    }

    // epilogue
    #pragma unroll
    for (int mt = 0; mt < 4; mt++) {
        int r0 = m0 + wrow + mt * 16 + g;
        #pragma unroll
        for (int nt = 0; nt < 8; nt++) {
            int c = n0 + wcol + nt * 8 + 2 * tg;
            float b0 = 0.f, b1 = 0.f;
            if (EPI >= 1) { b0 = bias[c]; b1 = bias[c + 1]; }
            float v00 = acc[mt][nt][0] + b0, v01 = acc[mt][nt][1] + b1;
            float v10 = acc[mt][nt][2] + b0, v11 = acc[mt][nt][3] + b1;
            if (EPI == 2) {
                v00 = gelu_exact(v00); v01 = gelu_exact(v01);
                v10 = gelu_exact(v10); v11 = gelu_exact(v11);
            }
            *reinterpret_cast<float2*>(C + (size_t)r0 * N + c)       = make_float2(v00, v01);
            *reinterpret_cast<float2*>(C + (size_t)(r0 + 8) * N + c) = make_float2(v10, v11);
        }
    }
}

// ---------------- tf32 flash attention, 128-query tiles -------------------
// grid (S/128, H, B), 128 threads (4 warps). Each warp owns two 16-row
// query bands (h=0: rows 16w..16w+15; h=1: rows 64+16w..). K/V fragments are
// loaded once per iteration and reused across both bands.
__launch_bounds__(128, 2)
__global__ void flash_tc_kernel(const float* __restrict__ qkv,
                                const int* __restrict__ mask,
                                float* __restrict__ out) {
    __shared__ __align__(16) float Ks[3][32][68];   // also Q staging [64][68]
    __shared__ __align__(16) float Vs[3][32][72];
    __shared__ float Ps[128][36];
    __shared__ __align__(16) int msk[3][32];

    const int b = blockIdx.z, h_ = blockIdx.y;
    const int q0 = blockIdx.x * 128;
    const int tid = threadIdx.x, lane = tid & 31, warp = tid >> 5;
    const int g = lane >> 2, tg = lane & 3;
    const size_t base = (size_t)b * SS;
    const int qcol = h_ * HDIM;

    // stage Q (scaled by 0.125) in two 64-row halves through Ks region
    float* qst = &Ks[0][0][0];
    uint32_t qf[2][8][4];
    #pragma unroll
    for (int half = 0; half < 2; half++) {
        #pragma unroll
        for (int i = 0; i < 8; i++) {
            int idx = tid + 128 * i;          // 1024 float4 = 64 rows x 16
            int r = idx >> 4, c = (idx & 15) * 4;
            float4 v = *reinterpret_cast<const float4*>(
                qkv + (base + q0 + half * 64 + r) * (3 * DD) + qcol + c);
            qst[r * 68 + c]     = v.x * 0.125f;
            qst[r * 68 + c + 1] = v.y * 0.125f;
            qst[r * 68 + c + 2] = v.z * 0.125f;
            qst[r * 68 + c + 3] = v.w * 0.125f;
        }
        __syncthreads();
        #pragma unroll
        for (int ks = 0; ks < 8; ks++) {
            int r = warp * 16 + g, c = ks * 8 + tg;
            qf[half][ks][0] = __float_as_uint(qst[r * 68 + c]);
            qf[half][ks][1] = __float_as_uint(qst[(r + 8) * 68 + c]);
            qf[half][ks][2] = __float_as_uint(qst[r * 68 + c + 4]);
            qf[half][ks][3] = __float_as_uint(qst[(r + 8) * 68 + c + 4]);
        }
        __syncthreads();   // reads done before next half / KV pipeline
    }

    auto issueKV = [&](int st, int kc) {
        #pragma unroll
        for (int i = 0; i < 4; i++) {
            int idx = tid + 128 * i;
            int r = idx >> 4, c = (idx & 15) * 4;
            const float* src = qkv + (base + kc + r) * (3 * DD) + qcol;
            cp16(smem_u32(&Ks[st][r][c]), src + DD + c);
            cp16(smem_u32(&Vs[st][r][c]), src + 2 * DD + c);
        }
        if (tid < 8) cp16(smem_u32(&msk[st][tid * 4]), mask + b * SS + kc + tid * 4);
    };

    float o[2][8][4];
    #pragma unroll
    for (int h = 0; h < 2; h++)
        #pragma unroll
        for (int nt = 0; nt < 8; nt++)
            #pragma unroll
            for (int r = 0; r < 4; r++) o[h][nt][r] = 0.f;
    float mprev[2][2] = {{-1e30f, -1e30f}, {-1e30f, -1e30f}};
    float lsum[2][2]  = {{0.f, 0.f}, {0.f, 0.f}};

    const int nIter = SS / 32;   // 64
    issueKV(0, 0);  cp_commit();
    issueKV(1, 32); cp_commit();

    for (int it = 0; it < nIter; it++) {
        if (it == nIter - 1) cp_wait<0>(); else cp_wait<1>();
        __syncthreads();
        if (it + 2 < nIter) { issueKV((it + 2) % 3, (it + 2) * 32); cp_commit(); }
        const int st = it % 3;

        // S = Q K^T for both halves; K fragments loaded once per ks
        float s[2][4][4];
        #pragma unroll
        for (int h = 0; h < 2; h++)
            #pragma unroll
            for (int nt = 0; nt < 4; nt++)
                #pragma unroll
                for (int r = 0; r < 4; r++) s[h][nt][r] = 0.f;
        #pragma unroll
        for (int ks = 0; ks < 8; ks++) {
            uint32_t kb[4][2];
            #pragma unroll
            for (int nt = 0; nt < 4; nt++) {
                kb[nt][0] = __float_as_uint(Ks[st][nt * 8 + g][ks * 8 + tg]);
                kb[nt][1] = __float_as_uint(Ks[st][nt * 8 + g][ks * 8 + tg + 4]);
            }
            #pragma unroll
            for (int h = 0; h < 2; h++)
                #pragma unroll
                for (int nt = 0; nt < 4; nt++)
                    mma_tf32(s[h][nt], qf[h][ks], kb[nt][0], kb[nt][1]);
        }

        // mask + softmax per half
        float alpha[2][2];
        #pragma unroll
        for (int h = 0; h < 2; h++) {
            float mx0 = -1e30f, mx1 = -1e30f;
            #pragma unroll
            for (int nt = 0; nt < 4; nt++) {
                int c = nt * 8 + 2 * tg;
                if (msk[st][c] == 0)     { s[h][nt][0] = -1e30f; s[h][nt][2] = -1e30f; }
                if (msk[st][c + 1] == 0) { s[h][nt][1] = -1e30f; s[h][nt][3] = -1e30f; }
                mx0 = fmaxf(mx0, fmaxf(s[h][nt][0], s[h][nt][1]));
                mx1 = fmaxf(mx1, fmaxf(s[h][nt][2], s[h][nt][3]));
            }
            mx0 = fmaxf(mx0, __shfl_xor_sync(0xffffffffu, mx0, 1));
            mx0 = fmaxf(mx0, __shfl_xor_sync(0xffffffffu, mx0, 2));
            mx1 = fmaxf(mx1, __shfl_xor_sync(0xffffffffu, mx1, 1));
            mx1 = fmaxf(mx1, __shfl_xor_sync(0xffffffffu, mx1, 2));

            float mn0 = fmaxf(mprev[h][0], mx0), mn1 = fmaxf(mprev[h][1], mx1);
            alpha[h][0] = __expf(mprev[h][0] - mn0);
            alpha[h][1] = __expf(mprev[h][1] - mn1);

            float ps0 = 0.f, ps1 = 0.f;
            #pragma unroll
            for (int nt = 0; nt < 4; nt++) {
                s[h][nt][0] = __expf(s[h][nt][0] - mn0);
                s[h][nt][1] = __expf(s[h][nt][1] - mn0);
                s[h][nt][2] = __expf(s[h][nt][2] - mn1);
                s[h][nt][3] = __expf(s[h][nt][3] - mn1);
                ps0 += s[h][nt][0] + s[h][nt][1];
                ps1 += s[h][nt][2] + s[h][nt][3];
                int r = h * 64 + warp * 16 + g, c = nt * 8 + 2 * tg;
                Ps[r][c]         = s[h][nt][0];
                Ps[r][c + 1]     = s[h][nt][1];
                Ps[r + 8][c]     = s[h][nt][2];
                Ps[r + 8][c + 1] = s[h][nt][3];
            }
            lsum[h][0] = lsum[h][0] * alpha[h][0] + ps0;
            lsum[h][1] = lsum[h][1] * alpha[h][1] + ps1;
            mprev[h][0] = mn0; mprev[h][1] = mn1;
        }
        __syncwarp();   // P writes visible before frag reads (warp-local rows)

        // O = O*alpha + P V; V fragments loaded once per ks
        #pragma unroll
        for (int h = 0; h < 2; h++)
            #pragma unroll
            for (int nt = 0; nt < 8; nt++) {
                o[h][nt][0] *= alpha[h][0]; o[h][nt][1] *= alpha[h][0];
                o[h][nt][2] *= alpha[h][1]; o[h][nt][3] *= alpha[h][1];
            }
        #pragma unroll
        for (int ks = 0; ks < 4; ks++) {
            uint32_t vb[8][2];
            #pragma unroll
            for (int nt = 0; nt < 8; nt++) {
                vb[nt][0] = __float_as_uint(Vs[st][ks * 8 + tg][nt * 8 + g]);
                vb[nt][1] = __float_as_uint(Vs[st][ks * 8 + tg + 4][nt * 8 + g]);
            }
            #pragma unroll
            for (int h = 0; h < 2; h++) {
                uint32_t af[4];
                int r = h * 64 + warp * 16 + g, c = ks * 8 + tg;
                af[0] = __float_as_uint(Ps[r][c]);
                af[1] = __float_as_uint(Ps[r + 8][c]);
                af[2] = __float_as_uint(Ps[r][c + 4]);
                af[3] = __float_as_uint(Ps[r + 8][c + 4]);
                #pragma unroll
                for (int nt = 0; nt < 8; nt++)
                    mma_tf32(o[h][nt], af, vb[nt][0], vb[nt][1]);
            }
        }
        __syncwarp();   // P reads done before next chunk rewrites warp rows
    }

    #pragma unroll
    for (int h = 0; h < 2; h++) {
        float l0 = lsum[h][0], l1 = lsum[h][1];
        l0 += __shfl_xor_sync(0xffffffffu, l0, 1);
        l0 += __shfl_xor_sync(0xffffffffu, l0, 2);
        l1 += __shfl_xor_sync(0xffffffffu, l1, 1);
        l1 += __shfl_xor_sync(0xffffffffu, l1, 2);
        float inv0 = 1.0f / l0, inv1 = 1.0f / l1;

        int r0 = q0 + h * 64 + warp * 16 + g;
        #pragma unroll
        for (int nt = 0; nt < 8; nt++) {
            int c = qcol + nt * 8 + 2 * tg;
            *reinterpret_cast<float2*>(out + (base + r0) * DD + c) =
                make_float2(o[h][nt][0] * inv0, o[h][nt][1] * inv0);
            *reinterpret_cast<float2*>(out + (base + r0 + 8) * DD + c) =
                make_float2(o[h][nt][2] * inv1, o[h][nt][3] * inv1);
        }
    }
}

// ---------------- residual add + LayerNorm (in-place into X) --------------
__device__ __forceinline__ float block_reduce_256(float v, float* red) {
    __syncthreads();
    int t = threadIdx.x;
    #pragma unroll
    for (int o = 16; o > 0; o >>= 1) v += __shfl_down_sync(0xffffffffu, v, o);
    if ((t & 31) == 0) red[t >> 5] = v;
    __syncthreads();
    if (t < 8) {
        v = red[t];
        #pragma unroll
        for (int o = 4; o > 0; o >>= 1) v += __shfl_down_sync(0xffu, v, o);
        if (t == 0) red[0] = v;
    }
    __syncthreads();
    return red[0];
}

__global__ void add_ln_kernel(const float* __restrict__ A,
                              float* __restrict__ X,
                              const float* __restrict__ g,
                              const float* __restrict__ bt) {
    __shared__ float red[32];
    int r = blockIdx.x, t = threadIdx.x;
    const float* a = A + (size_t)r * DD;
    float* x = X + (size_t)r * DD;
    float v[4];
    float sum = 0.f;
    #pragma unroll
    for (int i = 0; i < 4; i++) {
        int d = t + 256 * i;
        v[i] = a[d] + x[d];
        sum += v[i];
    }
    sum = block_reduce_256(sum, red);
    float mu = sum * (1.0f / DD);
    float vs = 0.f;
    #pragma unroll
    for (int i = 0; i < 4; i++) {
        float dl = v[i] - mu;
        vs += dl * dl;
    }
    vs = block_reduce_256(vs, red);
    float rs = rsqrtf(vs * (1.0f / DD) + 1e-5f);
    #pragma unroll
    for (int i = 0; i < 4; i++) {
        int d = t + 256 * i;
        x[d] = (v[i] - mu) * rs * g[d] + bt[d];
    }
}

// ---------------- masked max-pool over sequence ----------------
__global__ void pool_partial_kernel(const float* __restrict__ X,
                                    const int* __restrict__ mask,
                                    float* __restrict__ part) {
    int b = blockIdx.y, ch = blockIdx.x;
    int d = threadIdx.x;
    float m = -INFINITY;
    for (int s = 0; s < 128; s++) {
        int srow = ch * 128 + s;
        float val = X[((size_t)b * SS + srow) * DD + d];
        if (mask[b * SS + srow] != 0) m = fmaxf(m, val);
    }
    part[((size_t)b * 16 + ch) * DD + d] = m;
}

__global__ void pool_final_kernel(const float* __restrict__ part,
                                  float* __restrict__ pooled) {
    int b = blockIdx.x, d = threadIdx.x;
    float m = -INFINITY;
    for (int c = 0; c < 16; c++)
        m = fmaxf(m, part[((size_t)b * 16 + c) * DD + d]);
    pooled[b * DD + d] = m;
}

// ---------------- small head FC ----------------
__global__ void head_fc_kernel(const float* __restrict__ in,
                               const float* __restrict__ W,
                               const float* __restrict__ bias,
                               float* __restrict__ out,
                               int K, int apply_gelu) {
    __shared__ float red[4];
    int n = blockIdx.x, b = blockIdx.y, t = threadIdx.x;
    int N = gridDim.x;
    const float* ip = in + (size_t)b * K;
    const float* wp = W + (size_t)n * K;
    float s = 0.f;
    for (int k = t; k < K; k += 128) s += ip[k] * wp[k];
    #pragma unroll
    for (int o = 16; o > 0; o >>= 1) s += __shfl_down_sync(0xffffffffu, s, o);
    if ((t & 31) == 0) red[t >> 5] = s;
    __syncthreads();
    if (t == 0) {
        float v = red[0] + red[1] + red[2] + red[3] + bias[n];
        if (apply_gelu) v = gelu_exact(v);
        out[b * N + n] = v;
    }
}

// ---------------- launch ----------------
extern "C" void kernel_launch(void* const* d_in, const int* in_sizes, int n_in,
                              void* d_out, int out_size) {
    const int*   x_ids  = (const int*)d_in[0];
    const int*   mask   = (const int*)d_in[1];
    const float* emb    = (const float*)d_in[2];
    const float* qkv_w  = (const float*)d_in[3];
    const float* fc_w   = (const float*)d_in[4];
    const float* fc_b   = (const float*)d_in[5];
    const float* ln1_g  = (const float*)d_in[6];
    const float* ln1_b  = (const float*)d_in[7];
    const float* ffn_w1 = (const float*)d_in[8];
    const float* ffn_b1 = (const float*)d_in[9];
    const float* ffn_w2 = (const float*)d_in[10];
    const float* ffn_b2 = (const float*)d_in[11];
    const float* ln2_g  = (const float*)d_in[12];
    const float* ln2_b  = (const float*)d_in[13];
    const float* pr_w1  = (const float*)d_in[14];
    const float* pr_b1  = (const float*)d_in[15];
    const float* pr_w2  = (const float*)d_in[16];
    const float* pr_b2  = (const float*)d_in[17];
    float* out = (float*)d_out;

    float *X, *QKV, *AO, *O, *Hb, *part, *pool, *hh;
    cudaGetSymbolAddress((void**)&X,    g_X);
    cudaGetSymbolAddress((void**)&QKV,  g_QKV);
    cudaGetSymbolAddress((void**)&AO,   g_AO);
    cudaGetSymbolAddress((void**)&O,    g_O);
    cudaGetSymbolAddress((void**)&Hb,   g_H);
    cudaGetSymbolAddress((void**)&part, g_part);
    cudaGetSymbolAddress((void**)&pool, g_pool);
    cudaGetSymbolAddress((void**)&hh,   g_hh);

    // 1. embedding + positional encoding
    embed_pe_kernel<<<(NTOK * (DD / 2)) / 256, 256>>>(x_ids, emb, X);

    // 2. QKV projection
    gemm_tc_kernel<0><<<dim3(3 * DD / 128, NTOK / 128), 128>>>(
        X, qkv_w, nullptr, QKV, NTOK, 3 * DD, DD);

    // 3. attention (128-query tiles)
    flash_tc_kernel<<<dim3(SS / 128, HH, BB), 128>>>(QKV, mask, AO);

    // 4. output projection (+bias)
    gemm_tc_kernel<1><<<dim3(DD / 128, NTOK / 128), 128>>>(
        AO, fc_w, fc_b, O, NTOK, DD, DD);

    // 5. residual + LN1
    add_ln_kernel<<<NTOK, 256>>>(O, X, ln1_g, ln1_b);

    // 6. FFN up (+bias, gelu)
    gemm_tc_kernel<2><<<dim3(FFN / 128, NTOK / 128), 128>>>(
        X, ffn_w1, ffn_b1, Hb, NTOK, FFN, DD);

    // 7. FFN down (+bias)
    gemm_tc_kernel<1><<<dim3(DD / 128, NTOK / 128), 128>>>(
        Hb, ffn_w2, ffn_b2, O, NTOK, DD, FFN);

    // 8. residual + LN2
    add_ln_kernel<<<NTOK, 256>>>(O, X, ln2_g, ln2_b);

    // 9. masked max-pool
    pool_partial_kernel<<<dim3(16, BB), 1024>>>(X, mask, part);
    pool_final_kernel<<<BB, 1024>>>(part, pool);

    // 10. prediction head
    head_fc_kernel<<<dim3(DD, BB), 128>>>(pool, pr_w1, pr_b1, hh, DD, 1);
    head_fc_kernel<<<dim3(10, BB), 128>>>(hh, pr_w2, pr_b2, out, DD, 0);
}

// round 8
// speedup vs baseline: 7.1273x; 1.3749x over previous
#include <cuda_runtime.h>
#include <cuda_fp16.h>
#include <math.h>
#include <stdint.h>

// Problem constants
#define BB 4
#define SS 2048
#define DD 1024
#define HH 16
#define HDIM 64
#define FFN 2048
#define NTOK (BB*SS)          // 8192

// ---------------- scratch (device globals: allocation-free) ----------------
__device__ float  g_X   [NTOK * DD];          // fp32 residual stream
__device__ float  g_O   [NTOK * DD];          // fp32 gemm output
__device__ __half g_X16 [NTOK * DD];          // fp16 activation copy
__device__ __half g_QKV16[NTOK * 3 * DD];
__device__ __half g_Vt16 [BB * HH * HDIM * SS];  // V transposed [b,h,dim,seq]
__device__ __half g_AO16 [NTOK * DD];
__device__ __half g_H16  [NTOK * FFN];
__device__ __half g_Wq16 [3 * DD * DD];
__device__ __half g_Wf16 [DD * DD];
__device__ __half g_W116 [FFN * DD];
__device__ __half g_W216 [DD * FFN];
__device__ float  g_part[BB * 16 * DD];
__device__ float  g_pool[BB * DD];
__device__ float  g_hh  [BB * DD];

__device__ __forceinline__ float gelu_exact(float v) {
    return 0.5f * v * (1.0f + erff(v * 0.7071067811865476f));
}

__device__ __forceinline__ uint32_t smem_u32(const void* p) {
    return (uint32_t)__cvta_generic_to_shared(p);
}
__device__ __forceinline__ void cp16(uint32_t dst, const void* src) {
    asm volatile("cp.async.cg.shared.global [%0], [%1], 16;" :: "r"(dst), "l"(src));
}
__device__ __forceinline__ void cp_commit() {
    asm volatile("cp.async.commit_group;");
}
template<int N>
__device__ __forceinline__ void cp_wait() {
    asm volatile("cp.async.wait_group %0;" :: "n"(N));
}

// fp16 MMA, fp32 accumulate: m16n8k16
__device__ __forceinline__ void mma_f16(float* d, const uint32_t* a, uint32_t b0, uint32_t b1) {
    asm volatile(
        "mma.sync.aligned.m16n8k16.row.col.f32.f16.f16.f32 "
        "{%0,%1,%2,%3}, {%4,%5,%6,%7}, {%8,%9}, {%0,%1,%2,%3};\n"
        : "+f"(d[0]), "+f"(d[1]), "+f"(d[2]), "+f"(d[3])
        : "r"(a[0]), "r"(a[1]), "r"(a[2]), "r"(a[3]), "r"(b0), "r"(b1));
}

__device__ __forceinline__ uint32_t pack_half2(float a, float b) {
    __half2 h = __floats2half2_rn(a, b);
    uint32_t u;
    memcpy(&u, &h, 4);
    return u;
}

// ---------------- fp32 -> fp16 weight conversion ----------------
__global__ void f2h_kernel(const float* __restrict__ in, __half* __restrict__ out, int n) {
    int i = (blockIdx.x * blockDim.x + threadIdx.x) * 4;
    if (i >= n) return;
    float4 v = *reinterpret_cast<const float4*>(in + i);
    *reinterpret_cast<__half2*>(out + i)     = __floats2half2_rn(v.x, v.y);
    *reinterpret_cast<__half2*>(out + i + 2) = __floats2half2_rn(v.z, v.w);
}

// ---------------- embedding + positional encoding (fp32 + fp16) -----------
__global__ void embed_pe_kernel(const int* __restrict__ ids,
                                const float* __restrict__ emb,
                                float* __restrict__ X,
                                __half* __restrict__ X16) {
    int idx = blockIdx.x * blockDim.x + threadIdx.x;
    if (idx >= NTOK * (DD / 2)) return;
    int row = idx >> 9;
    int p   = idx & 511;
    int s   = row & (SS - 1);
    int id  = ids[row];
    float freq = expf(-0.017988946039015358f * (float)p);  // 2*ln(1e4)/1024
    float sv, cv;
    sincosf((float)s * freq, &sv, &cv);
    size_t eo = (size_t)id * DD + 2 * p;
    size_t xo = (size_t)row * DD + 2 * p;
    float v0 = emb[eo] + sv, v1 = emb[eo + 1] + cv;
    X[xo] = v0; X[xo + 1] = v1;
    *reinterpret_cast<__half2*>(X16 + xo) = __floats2half2_rn(v0, v1);
}

// ---------------- fp16 tensor-core GEMM: C = A(MxK) * W(NxK)^T ------------
// BM=BN=128, BK=16, 128 threads (4 warps 2x2), warp tile 64x64, k16 MMA.
template<int EPI, bool OUT16>   // EPI: 0 none, 1 +bias, 2 gelu(+bias)
__launch_bounds__(128, 2)
__global__ void gemm_f16_kernel(const __half* __restrict__ A,
                                const __half* __restrict__ W,
                                const float* __restrict__ bias,
                                float* __restrict__ Cf,
                                __half* __restrict__ Ch,
                                int M, int N, int K) {
    __shared__ __align__(16) uint32_t As[3][128][12];   // 8 u32 used, pad 12
    __shared__ __align__(16) uint32_t Ws[3][128][12];

    const int tid  = threadIdx.x;
    const int lane = tid & 31, warp = tid >> 5;
    const int wm = warp >> 1, wn = warp & 1;
    const int wrow = wm * 64, wcol = wn * 64;
    const int m0 = blockIdx.y * 128, n0 = blockIdx.x * 128;
    const int g = lane >> 2, tg = lane & 3;

    auto issue = [&](int st, int k0) {
        int r = tid;   // 0..127, one row each
        const __half* a = A + (size_t)(m0 + r) * K + k0;
        cp16(smem_u32(&As[st][r][0]), a);
        cp16(smem_u32(&As[st][r][4]), a + 8);
        const __half* w = W + (size_t)(n0 + r) * K + k0;
        cp16(smem_u32(&Ws[st][r][0]), w);
        cp16(smem_u32(&Ws[st][r][4]), w + 8);
    };

    float acc[4][8][4];
    #pragma unroll
    for (int mt = 0; mt < 4; mt++)
        #pragma unroll
        for (int nt = 0; nt < 8; nt++)
            #pragma unroll
            for (int r = 0; r < 4; r++) acc[mt][nt][r] = 0.f;

    const int nIter = K / 16;
    issue(0, 0);  cp_commit();
    issue(1, 16); cp_commit();

    for (int it = 0; it < nIter; it++) {
        if (it == nIter - 1) cp_wait<0>(); else cp_wait<1>();
        __syncthreads();
        if (it + 2 < nIter) { issue((it + 2) % 3, (it + 2) * 16); cp_commit(); }
        const int st = it % 3;

        uint32_t af[4][4], bf[8][2];
        #pragma unroll
        for (int mt = 0; mt < 4; mt++) {
            int r = wrow + mt * 16 + g;
            af[mt][0] = As[st][r][tg];
            af[mt][1] = As[st][r + 8][tg];
            af[mt][2] = As[st][r][tg + 4];
            af[mt][3] = As[st][r + 8][tg + 4];
        }
        #pragma unroll
        for (int nt = 0; nt < 8; nt++) {
            int n = wcol + nt * 8 + g;
            bf[nt][0] = Ws[st][n][tg];
            bf[nt][1] = Ws[st][n][tg + 4];
        }
        #pragma unroll
        for (int mt = 0; mt < 4; mt++)
            #pragma unroll
            for (int nt = 0; nt < 8; nt++)
                mma_f16(acc[mt][nt], af[mt], bf[nt][0], bf[nt][1]);
    }

    // epilogue
    #pragma unroll
    for (int mt = 0; mt < 4; mt++) {
        int r0 = m0 + wrow + mt * 16 + g;
        #pragma unroll
        for (int nt = 0; nt < 8; nt++) {
            int c = n0 + wcol + nt * 8 + 2 * tg;
            float b0 = 0.f, b1 = 0.f;
            if (EPI >= 1) { b0 = bias[c]; b1 = bias[c + 1]; }
            float v00 = acc[mt][nt][0] + b0, v01 = acc[mt][nt][1] + b1;
            float v10 = acc[mt][nt][2] + b0, v11 = acc[mt][nt][3] + b1;
            if (EPI == 2) {
                v00 = gelu_exact(v00); v01 = gelu_exact(v01);
                v10 = gelu_exact(v10); v11 = gelu_exact(v11);
            }
            if (OUT16) {
                *reinterpret_cast<__half2*>(Ch + (size_t)r0 * N + c)       = __floats2half2_rn(v00, v01);
                *reinterpret_cast<__half2*>(Ch + (size_t)(r0 + 8) * N + c) = __floats2half2_rn(v10, v11);
            } else {
                *reinterpret_cast<float2*>(Cf + (size_t)r0 * N + c)       = make_float2(v00, v01);
                *reinterpret_cast<float2*>(Cf + (size_t)(r0 + 8) * N + c) = make_float2(v10, v11);
            }
        }
    }
}

// ---------------- V transpose: qkv16 V-part -> Vt [b,h,dim,seq] -----------
__global__ void transpose_v_kernel(const __half* __restrict__ qkv16,
                                   __half* __restrict__ vt) {
    __shared__ __half t[32][33];
    int bh = blockIdx.z;
    int b = bh >> 4, h = bh & 15;
    int s0 = blockIdx.x * 32, d0 = blockIdx.y * 32;
    int tx = threadIdx.x, ty = threadIdx.y;   // 32 x 8
    #pragma unroll
    for (int i = 0; i < 4; i++) {
        int s = s0 + ty + i * 8;
        t[ty + i * 8][tx] = qkv16[((size_t)b * SS + s) * (3 * DD) + 2 * DD + h * HDIM + d0 + tx];
    }
    __syncthreads();
    #pragma unroll
    for (int i = 0; i < 4; i++) {
        int d = d0 + ty + i * 8;
        vt[((size_t)bh * HDIM + d) * SS + s0 + tx] = t[tx][ty + i * 8];
    }
}

// ---------------- fp16 flash attention, 128-query tiles -------------------
// grid (S/128, H, B), 128 threads (4 warps), k16 MMA, 32-key chunks.
__launch_bounds__(128, 2)
__global__ void flash_f16_kernel(const __half* __restrict__ qkv16,
                                 const __half* __restrict__ vt,
                                 const int* __restrict__ mask,
                                 __half* __restrict__ out16) {
    __shared__ __align__(16) uint32_t Ks[3][32][36];   // keys x dim-pairs; also Q staging
    __shared__ __align__(16) uint32_t Vst[3][64][20];  // dim x key-pairs
    __shared__ uint32_t Ps[128][20];                   // q-rows x key-pairs (fp16)
    __shared__ __align__(16) int msk[3][32];

    const int b = blockIdx.z, h_ = blockIdx.y;
    const int q0 = blockIdx.x * 128;
    const int tid = threadIdx.x, lane = tid & 31, warp = tid >> 5;
    const int g = lane >> 2, tg = lane & 3;
    const size_t base = (size_t)b * SS;
    const int qcol = h_ * HDIM;
    const size_t vtbase = ((size_t)(b * HH + h_)) * HDIM;

    // stage Q fp16 in two 64-row halves through the Ks region
    uint32_t* qst = &Ks[0][0][0];        // viewed as [64][36]
    uint32_t qf[2][4][4];
    #pragma unroll
    for (int half = 0; half < 2; half++) {
        #pragma unroll
        for (int i = 0; i < 4; i++) {
            int idx = tid + 128 * i;      // 512 16B-chunks = 64 rows x 8
            int r = idx >> 3, cj = idx & 7;
            uint4 v = *reinterpret_cast<const uint4*>(
                qkv16 + (base + q0 + half * 64 + r) * (3 * DD) + qcol + cj * 8);
            *reinterpret_cast<uint4*>(&qst[r * 36 + cj * 4]) = v;
        }
        __syncthreads();
        #pragma unroll
        for (int ks = 0; ks < 4; ks++) {
            int r = warp * 16 + g;
            qf[half][ks][0] = qst[r * 36 + ks * 8 + tg];
            qf[half][ks][1] = qst[(r + 8) * 36 + ks * 8 + tg];
            qf[half][ks][2] = qst[r * 36 + ks * 8 + tg + 4];
            qf[half][ks][3] = qst[(r + 8) * 36 + ks * 8 + tg + 4];
        }
        __syncthreads();
    }

    auto issueKV = [&](int st, int kc) {
        // K: 32 key-rows x 64 dims fp16 = 128B/row -> 8 cp16 each
        #pragma unroll
        for (int i = 0; i < 2; i++) {
            int e = tid + 128 * i;         // 0..255
            int r = e >> 3, cj = e & 7;
            cp16(smem_u32(&Ks[st][r][cj * 4]),
                 qkv16 + (base + kc + r) * (3 * DD) + DD + qcol + cj * 8);
        }
        // V^T: 64 dim-rows x 32 keys fp16 = 64B/row -> 4 cp16 each
        #pragma unroll
        for (int i = 0; i < 2; i++) {
            int e = tid + 128 * i;         // 0..255
            int r = e >> 2, cj = e & 3;
            cp16(smem_u32(&Vst[st][r][cj * 4]),
                 vt + (vtbase + r) * SS + kc + cj * 8);
        }
        if (tid < 8) cp16(smem_u32(&msk[st][tid * 4]), mask + b * SS + kc + tid * 4);
    };

    float o[2][8][4];
    #pragma unroll
    for (int h = 0; h < 2; h++)
        #pragma unroll
        for (int nt = 0; nt < 8; nt++)
            #pragma unroll
            for (int r = 0; r < 4; r++) o[h][nt][r] = 0.f;
    float mprev[2][2] = {{-1e30f, -1e30f}, {-1e30f, -1e30f}};
    float lsum[2][2]  = {{0.f, 0.f}, {0.f, 0.f}};

    const int nIter = SS / 32;   // 64
    issueKV(0, 0);  cp_commit();
    issueKV(1, 32); cp_commit();

    for (int it = 0; it < nIter; it++) {
        if (it == nIter - 1) cp_wait<0>(); else cp_wait<1>();
        __syncthreads();
        if (it + 2 < nIter) { issueKV((it + 2) % 3, (it + 2) * 32); cp_commit(); }
        const int st = it % 3;

        // S = Q K^T (fp16 MMA, contraction over 64 dims = 4 k16 steps)
        float s[2][4][4];
        #pragma unroll
        for (int h = 0; h < 2; h++)
            #pragma unroll
            for (int nt = 0; nt < 4; nt++)
                #pragma unroll
                for (int r = 0; r < 4; r++) s[h][nt][r] = 0.f;
        #pragma unroll
        for (int ks = 0; ks < 4; ks++) {
            uint32_t kb[4][2];
            #pragma unroll
            for (int nt = 0; nt < 4; nt++) {
                kb[nt][0] = Ks[st][nt * 8 + g][ks * 8 + tg];
                kb[nt][1] = Ks[st][nt * 8 + g][ks * 8 + tg + 4];
            }
            #pragma unroll
            for (int h = 0; h < 2; h++)
                #pragma unroll
                for (int nt = 0; nt < 4; nt++)
                    mma_f16(s[h][nt], qf[h][ks], kb[nt][0], kb[nt][1]);
        }

        // scale + mask + online softmax per half
        float alpha[2][2];
        #pragma unroll
        for (int h = 0; h < 2; h++) {
            float mx0 = -1e30f, mx1 = -1e30f;
            #pragma unroll
            for (int nt = 0; nt < 4; nt++) {
                int c = nt * 8 + 2 * tg;
                s[h][nt][0] *= 0.125f; s[h][nt][1] *= 0.125f;
                s[h][nt][2] *= 0.125f; s[h][nt][3] *= 0.125f;
                if (msk[st][c] == 0)     { s[h][nt][0] = -1e30f; s[h][nt][2] = -1e30f; }
                if (msk[st][c + 1] == 0) { s[h][nt][1] = -1e30f; s[h][nt][3] = -1e30f; }
                mx0 = fmaxf(mx0, fmaxf(s[h][nt][0], s[h][nt][1]));
                mx1 = fmaxf(mx1, fmaxf(s[h][nt][2], s[h][nt][3]));
            }
            mx0 = fmaxf(mx0, __shfl_xor_sync(0xffffffffu, mx0, 1));
            mx0 = fmaxf(mx0, __shfl_xor_sync(0xffffffffu, mx0, 2));
            mx1 = fmaxf(mx1, __shfl_xor_sync(0xffffffffu, mx1, 1));
            mx1 = fmaxf(mx1, __shfl_xor_sync(0xffffffffu, mx1, 2));

            float mn0 = fmaxf(mprev[h][0], mx0), mn1 = fmaxf(mprev[h][1], mx1);
            alpha[h][0] = __expf(mprev[h][0] - mn0);
            alpha[h][1] = __expf(mprev[h][1] - mn1);

            float ps0 = 0.f, ps1 = 0.f;
            #pragma unroll
            for (int nt = 0; nt < 4; nt++) {
                float e00 = __expf(s[h][nt][0] - mn0);
                float e01 = __expf(s[h][nt][1] - mn0);
                float e10 = __expf(s[h][nt][2] - mn1);
                float e11 = __expf(s[h][nt][3] - mn1);
                ps0 += e00 + e01;
                ps1 += e10 + e11;
                int r = h * 64 + warp * 16 + g;
                Ps[r][nt * 4 + tg]     = pack_half2(e00, e01);
                Ps[r + 8][nt * 4 + tg] = pack_half2(e10, e11);
            }
            lsum[h][0] = lsum[h][0] * alpha[h][0] + ps0;
            lsum[h][1] = lsum[h][1] * alpha[h][1] + ps1;
            mprev[h][0] = mn0; mprev[h][1] = mn1;
        }
        __syncwarp();   // P writes visible before frag reads (warp-local rows)

        // O = O*alpha + P V  (contraction over 32 keys = 2 k16 steps)
        #pragma unroll
        for (int h = 0; h < 2; h++)
            #pragma unroll
            for (int nt = 0; nt < 8; nt++) {
                o[h][nt][0] *= alpha[h][0]; o[h][nt][1] *= alpha[h][0];
                o[h][nt][2] *= alpha[h][1]; o[h][nt][3] *= alpha[h][1];
            }
        #pragma unroll
        for (int ks = 0; ks < 2; ks++) {
            uint32_t vb[8][2];
            #pragma unroll
            for (int nt = 0; nt < 8; nt++) {
                vb[nt][0] = Vst[st][nt * 8 + g][ks * 8 + tg];
                vb[nt][1] = Vst[st][nt * 8 + g][ks * 8 + tg + 4];
            }
            #pragma unroll
            for (int h = 0; h < 2; h++) {
                uint32_t af[4];
                int r = h * 64 + warp * 16 + g;
                af[0] = Ps[r][ks * 8 + tg];
                af[1] = Ps[r + 8][ks * 8 + tg];
                af[2] = Ps[r][ks * 8 + tg + 4];
                af[3] = Ps[r + 8][ks * 8 + tg + 4];
                #pragma unroll
                for (int nt = 0; nt < 8; nt++)
                    mma_f16(o[h][nt], af, vb[nt][0], vb[nt][1]);
            }
        }
        __syncwarp();
    }

    #pragma unroll
    for (int h = 0; h < 2; h++) {
        float l0 = lsum[h][0], l1 = lsum[h][1];
        l0 += __shfl_xor_sync(0xffffffffu, l0, 1);
        l0 += __shfl_xor_sync(0xffffffffu, l0, 2);
        l1 += __shfl_xor_sync(0xffffffffu, l1, 1);
        l1 += __shfl_xor_sync(0xffffffffu, l1, 2);
        float inv0 = 1.0f / l0, inv1 = 1.0f / l1;

        int r0 = q0 + h * 64 + warp * 16 + g;
        #pragma unroll
        for (int nt = 0; nt < 8; nt++) {
            int c = qcol + nt * 8 + 2 * tg;
            *reinterpret_cast<__half2*>(out16 + (base + r0) * DD + c) =
                __floats2half2_rn(o[h][nt][0] * inv0, o[h][nt][1] * inv0);
            *reinterpret_cast<__half2*>(out16 + (base + r0 + 8) * DD + c) =
                __floats2half2_rn(o[h][nt][2] * inv1, o[h][nt][3] * inv1);
        }
    }
}

// ---------------- residual add + LayerNorm (fp32 + optional fp16 out) -----
__device__ __forceinline__ float block_reduce_256(float v, float* red) {
    __syncthreads();
    int t = threadIdx.x;
    #pragma unroll
    for (int o = 16; o > 0; o >>= 1) v += __shfl_down_sync(0xffffffffu, v, o);
    if ((t & 31) == 0) red[t >> 5] = v;
    __syncthreads();
    if (t < 8) {
        v = red[t];
        #pragma unroll
        for (int o = 4; o > 0; o >>= 1) v += __shfl_down_sync(0xffu, v, o);
        if (t == 0) red[0] = v;
    }
    __syncthreads();
    return red[0];
}

template<bool OUT16>
__global__ void add_ln_kernel(const float* __restrict__ A,
                              float* __restrict__ X,
                              __half* __restrict__ X16,
                              const float* __restrict__ g,
                              const float* __restrict__ bt) {
    __shared__ float red[32];
    int r = blockIdx.x, t = threadIdx.x;
    const float* a = A + (size_t)r * DD;
    float* x = X + (size_t)r * DD;
    int d0 = t * 4;
    float4 av = *reinterpret_cast<const float4*>(a + d0);
    float4 xv = *reinterpret_cast<const float4*>(x + d0);
    float v[4] = {av.x + xv.x, av.y + xv.y, av.z + xv.z, av.w + xv.w};
    float sum = v[0] + v[1] + v[2] + v[3];
    sum = block_reduce_256(sum, red);
    float mu = sum * (1.0f / DD);
    float vs = 0.f;
    #pragma unroll
    for (int i = 0; i < 4; i++) { float dl = v[i] - mu; vs += dl * dl; }
    vs = block_reduce_256(vs, red);
    float rs = rsqrtf(vs * (1.0f / DD) + 1e-5f);
    float o[4];
    #pragma unroll
    for (int i = 0; i < 4; i++)
        o[i] = (v[i] - mu) * rs * g[d0 + i] + bt[d0 + i];
    *reinterpret_cast<float4*>(x + d0) = make_float4(o[0], o[1], o[2], o[3]);
    if (OUT16) {
        __half* x16 = X16 + (size_t)r * DD + d0;
        *reinterpret_cast<__half2*>(x16)     = __floats2half2_rn(o[0], o[1]);
        *reinterpret_cast<__half2*>(x16 + 2) = __floats2half2_rn(o[2], o[3]);
    }
}

// ---------------- masked max-pool over sequence ----------------
__global__ void pool_partial_kernel(const float* __restrict__ X,
                                    const int* __restrict__ mask,
                                    float* __restrict__ part) {
    int b = blockIdx.y, ch = blockIdx.x;
    int d = threadIdx.x;
    float m = -INFINITY;
    for (int s = 0; s < 128; s++) {
        int srow = ch * 128 + s;
        float val = X[((size_t)b * SS + srow) * DD + d];
        if (mask[b * SS + srow] != 0) m = fmaxf(m, val);
    }
    part[((size_t)b * 16 + ch) * DD + d] = m;
}

__global__ void pool_final_kernel(const float* __restrict__ part,
                                  float* __restrict__ pooled) {
    int b = blockIdx.x, d = threadIdx.x;
    float m = -INFINITY;
    for (int c = 0; c < 16; c++)
        m = fmaxf(m, part[((size_t)b * 16 + c) * DD + d]);
    pooled[b * DD + d] = m;
}

// ---------------- small head FC ----------------
__global__ void head_fc_kernel(const float* __restrict__ in,
                               const float* __restrict__ W,
                               const float* __restrict__ bias,
                               float* __restrict__ out,
                               int K, int apply_gelu) {
    __shared__ float red[4];
    int n = blockIdx.x, b = blockIdx.y, t = threadIdx.x;
    int N = gridDim.x;
    const float* ip = in + (size_t)b * K;
    const float* wp = W + (size_t)n * K;
    float s = 0.f;
    for (int k = t; k < K; k += 128) s += ip[k] * wp[k];
    #pragma unroll
    for (int o = 16; o > 0; o >>= 1) s += __shfl_down_sync(0xffffffffu, s, o);
    if ((t & 31) == 0) red[t >> 5] = s;
    __syncthreads();
    if (t == 0) {
        float v = red[0] + red[1] + red[2] + red[3] + bias[n];
        if (apply_gelu) v = gelu_exact(v);
        out[b * N + n] = v;
    }
}

// ---------------- launch ----------------
extern "C" void kernel_launch(void* const* d_in, const int* in_sizes, int n_in,
                              void* d_out, int out_size) {
    const int*   x_ids  = (const int*)d_in[0];
    const int*   mask   = (const int*)d_in[1];
    const float* emb    = (const float*)d_in[2];
    const float* qkv_w  = (const float*)d_in[3];
    const float* fc_w   = (const float*)d_in[4];
    const float* fc_b   = (const float*)d_in[5];
    const float* ln1_g  = (const float*)d_in[6];
    const float* ln1_b  = (const float*)d_in[7];
    const float* ffn_w1 = (const float*)d_in[8];
    const float* ffn_b1 = (const float*)d_in[9];
    const float* ffn_w2 = (const float*)d_in[10];
    const float* ffn_b2 = (const float*)d_in[11];
    const float* ln2_g  = (const float*)d_in[12];
    const float* ln2_b  = (const float*)d_in[13];
    const float* pr_w1  = (const float*)d_in[14];
    const float* pr_b1  = (const float*)d_in[15];
    const float* pr_w2  = (const float*)d_in[16];
    const float* pr_b2  = (const float*)d_in[17];
    float* out = (float*)d_out;

    float *X, *O, *part, *pool, *hh;
    __half *X16, *QKV16, *Vt16, *AO16, *H16, *Wq16, *Wf16, *W116, *W216;
    cudaGetSymbolAddress((void**)&X,     g_X);
    cudaGetSymbolAddress((void**)&O,     g_O);
    cudaGetSymbolAddress((void**)&X16,   g_X16);
    cudaGetSymbolAddress((void**)&QKV16, g_QKV16);
    cudaGetSymbolAddress((void**)&Vt16,  g_Vt16);
    cudaGetSymbolAddress((void**)&AO16,  g_AO16);
    cudaGetSymbolAddress((void**)&H16,   g_H16);
    cudaGetSymbolAddress((void**)&Wq16,  g_Wq16);
    cudaGetSymbolAddress((void**)&Wf16,  g_Wf16);
    cudaGetSymbolAddress((void**)&W116,  g_W116);
    cudaGetSymbolAddress((void**)&W216,  g_W216);
    cudaGetSymbolAddress((void**)&part,  g_part);
    cudaGetSymbolAddress((void**)&pool,  g_pool);
    cudaGetSymbolAddress((void**)&hh,    g_hh);

    // 0. convert weights to fp16
    f2h_kernel<<<(3 * DD * DD / 4 + 255) / 256, 256>>>(qkv_w,  Wq16, 3 * DD * DD);
    f2h_kernel<<<(DD * DD / 4 + 255) / 256, 256>>>(fc_w,   Wf16, DD * DD);
    f2h_kernel<<<(FFN * DD / 4 + 255) / 256, 256>>>(ffn_w1, W116, FFN * DD);
    f2h_kernel<<<(DD * FFN / 4 + 255) / 256, 256>>>(ffn_w2, W216, DD * FFN);

    // 1. embedding + positional encoding (fp32 + fp16)
    embed_pe_kernel<<<(NTOK * (DD / 2)) / 256, 256>>>(x_ids, emb, X, X16);

    // 2. QKV projection -> fp16
    gemm_f16_kernel<0, true><<<dim3(3 * DD / 128, NTOK / 128), 128>>>(
        X16, Wq16, nullptr, nullptr, QKV16, NTOK, 3 * DD, DD);

    // 2b. transpose V
    transpose_v_kernel<<<dim3(SS / 32, HDIM / 32, BB * HH), dim3(32, 8)>>>(QKV16, Vt16);

    // 3. attention (fp16 MMA)
    flash_f16_kernel<<<dim3(SS / 128, HH, BB), 128>>>(QKV16, Vt16, mask, AO16);

    // 4. output projection (+bias) -> fp32
    gemm_f16_kernel<1, false><<<dim3(DD / 128, NTOK / 128), 128>>>(
        AO16, Wf16, fc_b, O, nullptr, NTOK, DD, DD);

    // 5. residual + LN1 (fp32 X + fp16 copy)
    add_ln_kernel<true><<<NTOK, 256>>>(O, X, X16, ln1_g, ln1_b);

    // 6. FFN up (+bias, gelu) -> fp16
    gemm_f16_kernel<2, true><<<dim3(FFN / 128, NTOK / 128), 128>>>(
        X16, W116, ffn_b1, nullptr, H16, NTOK, FFN, DD);

    // 7. FFN down (+bias) -> fp32
    gemm_f16_kernel<1, false><<<dim3(DD / 128, NTOK / 128), 128>>>(
        H16, W216, ffn_b2, O, nullptr, NTOK, DD, FFN);

    // 8. residual + LN2 (fp32 only)
    add_ln_kernel<false><<<NTOK, 256>>>(O, X, nullptr, ln2_g, ln2_b);

    // 9. masked max-pool
    pool_partial_kernel<<<dim3(16, BB), 1024>>>(X, mask, part);
    pool_final_kernel<<<BB, 1024>>>(part, pool);

    // 10. prediction head
    head_fc_kernel<<<dim3(DD, BB), 128>>>(pool, pr_w1, pr_b1, hh, DD, 1);
    head_fc_kernel<<<dim3(10, BB), 128>>>(hh, pr_w2, pr_b2, out, DD, 0);
}

// round 13
// speedup vs baseline: 8.0004x; 1.1225x over previous
#include <cuda_runtime.h>
#include <cuda_fp16.h>
#include <math.h>
#include <stdint.h>

// Problem constants
#define BB 4
#define SS 2048
#define DD 1024
#define HH 16
#define HDIM 64
#define FFN 2048
#define NTOK (BB*SS)          // 8192

// ---------------- scratch (device globals: allocation-free) ----------------
__device__ float  g_X   [NTOK * DD];          // fp32 residual stream
__device__ float  g_O   [NTOK * DD];          // fp32 gemm output
__device__ __half g_X16 [NTOK * DD];          // fp16 activation copy
__device__ __half g_QKV16[NTOK * 3 * DD];
__device__ __half g_Vt16 [BB * HH * HDIM * SS];  // V transposed [b,h,dim,seq]
__device__ __half g_AO16 [NTOK * DD];
__device__ __half g_H16  [NTOK * FFN];
__device__ __half g_Wq16 [3 * DD * DD];
__device__ __half g_Wf16 [DD * DD];
__device__ __half g_W116 [FFN * DD];
__device__ __half g_W216 [DD * FFN];
__device__ float  g_part[BB * 16 * DD];
__device__ float  g_pool[BB * DD];
__device__ float  g_hh  [BB * DD];

__device__ __forceinline__ float gelu_exact(float v) {
    return 0.5f * v * (1.0f + erff(v * 0.7071067811865476f));
}

__device__ __forceinline__ uint32_t smem_u32(const void* p) {
    return (uint32_t)__cvta_generic_to_shared(p);
}
__device__ __forceinline__ void cp16(uint32_t dst, const void* src) {
    asm volatile("cp.async.cg.shared.global [%0], [%1], 16;" :: "r"(dst), "l"(src));
}
__device__ __forceinline__ void cp_commit() {
    asm volatile("cp.async.commit_group;");
}
template<int N>
__device__ __forceinline__ void cp_wait() {
    asm volatile("cp.async.wait_group %0;" :: "n"(N));
}

// fp16 MMA, fp32 accumulate: m16n8k16
__device__ __forceinline__ void mma_f16(float* d, const uint32_t* a, uint32_t b0, uint32_t b1) {
    asm volatile(
        "mma.sync.aligned.m16n8k16.row.col.f32.f16.f16.f32 "
        "{%0,%1,%2,%3}, {%4,%5,%6,%7}, {%8,%9}, {%0,%1,%2,%3};\n"
        : "+f"(d[0]), "+f"(d[1]), "+f"(d[2]), "+f"(d[3])
        : "r"(a[0]), "r"(a[1]), "r"(a[2]), "r"(a[3]), "r"(b0), "r"(b1));
}

// non-trans ldmatrix x4: correct for A-type ([m][k] rows) AND B-type stored
// as [n][k] rows (lane L gets elem (row = L>>2, col pair = 2*(L%4)), which is
// exactly the mma B fragment when row=n, col=k).
__device__ __forceinline__ void ldsm_x4(uint32_t& r0, uint32_t& r1, uint32_t& r2, uint32_t& r3,
                                        uint32_t addr) {
    asm volatile("ldmatrix.sync.aligned.m8n8.x4.shared.b16 {%0,%1,%2,%3}, [%4];"
                 : "=r"(r0), "=r"(r1), "=r"(r2), "=r"(r3) : "r"(addr));
}

__device__ __forceinline__ uint32_t pack_half2(float a, float b) {
    __half2 h = __floats2half2_rn(a, b);
    uint32_t u;
    memcpy(&u, &h, 4);
    return u;
}

// ---------------- fp32 -> fp16 weight conversion ----------------
__global__ void f2h_kernel(const float* __restrict__ in, __half* __restrict__ out, int n) {
    int i = (blockIdx.x * blockDim.x + threadIdx.x) * 4;
    if (i >= n) return;
    float4 v = *reinterpret_cast<const float4*>(in + i);
    *reinterpret_cast<__half2*>(out + i)     = __floats2half2_rn(v.x, v.y);
    *reinterpret_cast<__half2*>(out + i + 2) = __floats2half2_rn(v.z, v.w);
}

// ---------------- embedding + positional encoding (fp32 + fp16) -----------
__global__ void embed_pe_kernel(const int* __restrict__ ids,
                                const float* __restrict__ emb,
                                float* __restrict__ X,
                                __half* __restrict__ X16) {
    int idx = blockIdx.x * blockDim.x + threadIdx.x;
    if (idx >= NTOK * (DD / 2)) return;
    int row = idx >> 9;
    int p   = idx & 511;
    int s   = row & (SS - 1);
    int id  = ids[row];
    float freq = expf(-0.017988946039015358f * (float)p);  // 2*ln(1e4)/1024
    float sv, cv;
    sincosf((float)s * freq, &sv, &cv);
    size_t eo = (size_t)id * DD + 2 * p;
    size_t xo = (size_t)row * DD + 2 * p;
    float v0 = emb[eo] + sv, v1 = emb[eo + 1] + cv;
    X[xo] = v0; X[xo + 1] = v1;
    *reinterpret_cast<__half2*>(X16 + xo) = __floats2half2_rn(v0, v1);
}

// ---------------- fp16 tensor-core GEMM: C = A(MxK) * W(NxK)^T ------------
// BM=BN=128, BK=16, 128 threads (4 warps 2x2), warp tile 64x64, k16 MMA.
// ldmatrix fragment loads: 4 x4 (A) + 4 x4 (B, [n][k] rows) per iter.
template<int EPI, bool OUT16>   // EPI: 0 none, 1 +bias, 2 gelu(+bias)
__launch_bounds__(128, 2)
__global__ void gemm_f16_kernel(const __half* __restrict__ A,
                                const __half* __restrict__ W,
                                const float* __restrict__ bias,
                                float* __restrict__ Cf,
                                __half* __restrict__ Ch,
                                int M, int N, int K) {
    __shared__ __align__(16) uint32_t As[3][128][12];   // 8 u32 used, row stride 48B
    __shared__ __align__(16) uint32_t Ws[3][128][12];

    const int tid  = threadIdx.x;
    const int lane = tid & 31, warp = tid >> 5;
    const int wm = warp >> 1, wn = warp & 1;
    const int wrow = wm * 64, wcol = wn * 64;
    const int m0 = blockIdx.y * 128, n0 = blockIdx.x * 128;
    const int g = lane >> 2, tg = lane & 3;

    // ldmatrix lane-address bases (stage 0, tile 0)
    const int lrow = lane & 7, sel = lane >> 3;
    // A x4: m0-7/k0-7, m8-15/k0-7, m0-7/k8-15, m8-15/k8-15
    const uint32_t aAddr0 = smem_u32(&As[0][wrow + lrow + (sel & 1) * 8][(sel >> 1) * 4]);
    // B x4 (non-trans, [n][k] rows): n0-7/k0-7, n0-7/k8-15, n8-15/k0-7, n8-15/k8-15
    const uint32_t bAddr0 = smem_u32(&Ws[0][wcol + lrow + ((sel >> 1) & 1) * 8][(sel & 1) * 4]);
    const uint32_t stageB = 128 * 48;    // 6144 bytes per stage

    auto issue = [&](int st, int k0) {
        int r = tid;   // 0..127, one row each
        const __half* a = A + (size_t)(m0 + r) * K + k0;
        cp16(smem_u32(&As[st][r][0]), a);
        cp16(smem_u32(&As[st][r][4]), a + 8);
        const __half* w = W + (size_t)(n0 + r) * K + k0;
        cp16(smem_u32(&Ws[st][r][0]), w);
        cp16(smem_u32(&Ws[st][r][4]), w + 8);
    };

    float acc[4][8][4];
    #pragma unroll
    for (int mt = 0; mt < 4; mt++)
        #pragma unroll
        for (int nt = 0; nt < 8; nt++)
            #pragma unroll
            for (int r = 0; r < 4; r++) acc[mt][nt][r] = 0.f;

    const int nIter = K / 16;
    issue(0, 0);  cp_commit();
    issue(1, 16); cp_commit();

    for (int it = 0; it < nIter; it++) {
        if (it == nIter - 1) cp_wait<0>(); else cp_wait<1>();
        __syncthreads();
        if (it + 2 < nIter) { issue((it + 2) % 3, (it + 2) * 16); cp_commit(); }
        const int st = it % 3;
        const uint32_t aS = aAddr0 + st * stageB;
        const uint32_t bS = bAddr0 + st * stageB;

        uint32_t af[4][4], bf[8][2];
        #pragma unroll
        for (int mt = 0; mt < 4; mt++)
            ldsm_x4(af[mt][0], af[mt][1], af[mt][2], af[mt][3], aS + mt * 16 * 48);
        #pragma unroll
        for (int ntp = 0; ntp < 4; ntp++)
            ldsm_x4(bf[2 * ntp][0], bf[2 * ntp][1], bf[2 * ntp + 1][0], bf[2 * ntp + 1][1],
                    bS + ntp * 16 * 48);
        #pragma unroll
        for (int mt = 0; mt < 4; mt++)
            #pragma unroll
            for (int nt = 0; nt < 8; nt++)
                mma_f16(acc[mt][nt], af[mt], bf[nt][0], bf[nt][1]);
    }

    // epilogue
    #pragma unroll
    for (int mt = 0; mt < 4; mt++) {
        int r0 = m0 + wrow + mt * 16 + g;
        #pragma unroll
        for (int nt = 0; nt < 8; nt++) {
            int c = n0 + wcol + nt * 8 + 2 * tg;
            float b0 = 0.f, b1 = 0.f;
            if (EPI >= 1) { b0 = bias[c]; b1 = bias[c + 1]; }
            float v00 = acc[mt][nt][0] + b0, v01 = acc[mt][nt][1] + b1;
            float v10 = acc[mt][nt][2] + b0, v11 = acc[mt][nt][3] + b1;
            if (EPI == 2) {
                v00 = gelu_exact(v00); v01 = gelu_exact(v01);
                v10 = gelu_exact(v10); v11 = gelu_exact(v11);
            }
            if (OUT16) {
                *reinterpret_cast<__half2*>(Ch + (size_t)r0 * N + c)       = __floats2half2_rn(v00, v01);
                *reinterpret_cast<__half2*>(Ch + (size_t)(r0 + 8) * N + c) = __floats2half2_rn(v10, v11);
            } else {
                *reinterpret_cast<float2*>(Cf + (size_t)r0 * N + c)       = make_float2(v00, v01);
                *reinterpret_cast<float2*>(Cf + (size_t)(r0 + 8) * N + c) = make_float2(v10, v11);
            }
        }
    }
}

// ---------------- V transpose: qkv16 V-part -> Vt [b,h,dim,seq] -----------
__global__ void transpose_v_kernel(const __half* __restrict__ qkv16,
                                   __half* __restrict__ vt) {
    __shared__ __half t[32][33];
    int bh = blockIdx.z;
    int b = bh >> 4, h = bh & 15;
    int s0 = blockIdx.x * 32, d0 = blockIdx.y * 32;
    int tx = threadIdx.x, ty = threadIdx.y;   // 32 x 8
    #pragma unroll
    for (int i = 0; i < 4; i++) {
        int s = s0 + ty + i * 8;
        t[ty + i * 8][tx] = qkv16[((size_t)b * SS + s) * (3 * DD) + 2 * DD + h * HDIM + d0 + tx];
    }
    __syncthreads();
    #pragma unroll
    for (int i = 0; i < 4; i++) {
        int d = d0 + ty + i * 8;
        vt[((size_t)bh * HDIM + d) * SS + s0 + tx] = t[tx][ty + i * 8];
    }
}

// ---------------- fp16 flash attention, 128-query tiles, ldmatrix ---------
__launch_bounds__(128, 2)
__global__ void flash_f16_kernel(const __half* __restrict__ qkv16,
                                 const __half* __restrict__ vt,
                                 const int* __restrict__ mask,
                                 __half* __restrict__ out16) {
    __shared__ __align__(16) uint32_t Ks[3][32][36];   // keys x dim-u32 (144B rows); also Q staging
    __shared__ __align__(16) uint32_t Vst[3][64][20];  // dim x key-u32 (80B rows)
    __shared__ __align__(16) uint32_t Ps[128][20];     // q-rows x key-u32 fp16 (80B rows)
    __shared__ __align__(16) int msk[3][32];

    const int b = blockIdx.z, h_ = blockIdx.y;
    const int q0 = blockIdx.x * 128;
    const int tid = threadIdx.x, lane = tid & 31, warp = tid >> 5;
    const int g = lane >> 2, tg = lane & 3;
    const size_t base = (size_t)b * SS;
    const int qcol = h_ * HDIM;
    const size_t vtbase = ((size_t)(b * HH + h_)) * HDIM;

    const int lrow = lane & 7, sel = lane >> 3;
    // K/V non-trans B-type bases ([n][k] rows): n0-7/k0-7, n0-7/k8-15, n8-15/k0-7, n8-15/k8-15
    const uint32_t kAddr0 = smem_u32(&Ks[0][lrow + ((sel >> 1) & 1) * 8][(sel & 1) * 4]);
    const uint32_t vAddr0 = smem_u32(&Vst[0][lrow + ((sel >> 1) & 1) * 8][(sel & 1) * 4]);
    // P x4 base (A-type): m0-7/k0-7, m8-15/k0-7, m0-7/k8-15, m8-15/k8-15
    const uint32_t pAddr0 = smem_u32(&Ps[lrow + (sel & 1) * 8][(sel >> 1) * 4]);
    const uint32_t kStage = 32 * 144, vStage = 64 * 80;

    // stage Q fp16 in two 64-row halves through the Ks region
    uint32_t* qst = &Ks[0][0][0];        // viewed as [64][36]
    uint32_t qf[2][4][4];
    #pragma unroll
    for (int half = 0; half < 2; half++) {
        #pragma unroll
        for (int i = 0; i < 4; i++) {
            int idx = tid + 128 * i;      // 512 16B-chunks = 64 rows x 8
            int r = idx >> 3, cj = idx & 7;
            uint4 v = *reinterpret_cast<const uint4*>(
                qkv16 + (base + q0 + half * 64 + r) * (3 * DD) + qcol + cj * 8);
            *reinterpret_cast<uint4*>(&qst[r * 36 + cj * 4]) = v;
        }
        __syncthreads();
        #pragma unroll
        for (int ks = 0; ks < 4; ks++) {
            int r = warp * 16 + g;
            qf[half][ks][0] = qst[r * 36 + ks * 8 + tg];
            qf[half][ks][1] = qst[(r + 8) * 36 + ks * 8 + tg];
            qf[half][ks][2] = qst[r * 36 + ks * 8 + tg + 4];
            qf[half][ks][3] = qst[(r + 8) * 36 + ks * 8 + tg + 4];
        }
        __syncthreads();
    }

    auto issueKV = [&](int st, int kc) {
        #pragma unroll
        for (int i = 0; i < 2; i++) {
            int e = tid + 128 * i;         // 0..255
            int r = e >> 3, cj = e & 7;
            cp16(smem_u32(&Ks[st][r][cj * 4]),
                 qkv16 + (base + kc + r) * (3 * DD) + DD + qcol + cj * 8);
        }
        #pragma unroll
        for (int i = 0; i < 2; i++) {
            int e = tid + 128 * i;         // 0..255
            int r = e >> 2, cj = e & 3;
            cp16(smem_u32(&Vst[st][r][cj * 4]),
                 vt + (vtbase + r) * SS + kc + cj * 8);
        }
        if (tid < 8) cp16(smem_u32(&msk[st][tid * 4]), mask + b * SS + kc + tid * 4);
    };

    float o[2][8][4];
    #pragma unroll
    for (int h = 0; h < 2; h++)
        #pragma unroll
        for (int nt = 0; nt < 8; nt++)
            #pragma unroll
            for (int r = 0; r < 4; r++) o[h][nt][r] = 0.f;
    float mprev[2][2] = {{-1e30f, -1e30f}, {-1e30f, -1e30f}};
    float lsum[2][2]  = {{0.f, 0.f}, {0.f, 0.f}};

    const int nIter = SS / 32;   // 64
    issueKV(0, 0);  cp_commit();
    issueKV(1, 32); cp_commit();

    for (int it = 0; it < nIter; it++) {
        if (it == nIter - 1) cp_wait<0>(); else cp_wait<1>();
        __syncthreads();
        if (it + 2 < nIter) { issueKV((it + 2) % 3, (it + 2) * 32); cp_commit(); }
        const int st = it % 3;
        const uint32_t kS = kAddr0 + st * kStage;
        const uint32_t vS = vAddr0 + st * vStage;

        // S = Q K^T (4 k16 steps over 64 dims)
        float s[2][4][4];
        #pragma unroll
        for (int h = 0; h < 2; h++)
            #pragma unroll
            for (int nt = 0; nt < 4; nt++)
                #pragma unroll
                for (int r = 0; r < 4; r++) s[h][nt][r] = 0.f;
        #pragma unroll
        for (int ks = 0; ks < 4; ks++) {
            uint32_t kb[4][2];
            ldsm_x4(kb[0][0], kb[0][1], kb[1][0], kb[1][1], kS + ks * 32);
            ldsm_x4(kb[2][0], kb[2][1], kb[3][0], kb[3][1], kS + 16 * 144 + ks * 32);
            #pragma unroll
            for (int h = 0; h < 2; h++)
                #pragma unroll
                for (int nt = 0; nt < 4; nt++)
                    mma_f16(s[h][nt], qf[h][ks], kb[nt][0], kb[nt][1]);
        }

        // scale + mask + online softmax per half
        float alpha[2][2];
        #pragma unroll
        for (int h = 0; h < 2; h++) {
            float mx0 = -1e30f, mx1 = -1e30f;
            #pragma unroll
            for (int nt = 0; nt < 4; nt++) {
                int c = nt * 8 + 2 * tg;
                s[h][nt][0] *= 0.125f; s[h][nt][1] *= 0.125f;
                s[h][nt][2] *= 0.125f; s[h][nt][3] *= 0.125f;
                if (msk[st][c] == 0)     { s[h][nt][0] = -1e30f; s[h][nt][2] = -1e30f; }
                if (msk[st][c + 1] == 0) { s[h][nt][1] = -1e30f; s[h][nt][3] = -1e30f; }
                mx0 = fmaxf(mx0, fmaxf(s[h][nt][0], s[h][nt][1]));
                mx1 = fmaxf(mx1, fmaxf(s[h][nt][2], s[h][nt][3]));
            }
            mx0 = fmaxf(mx0, __shfl_xor_sync(0xffffffffu, mx0, 1));
            mx0 = fmaxf(mx0, __shfl_xor_sync(0xffffffffu, mx0, 2));
            mx1 = fmaxf(mx1, __shfl_xor_sync(0xffffffffu, mx1, 1));
            mx1 = fmaxf(mx1, __shfl_xor_sync(0xffffffffu, mx1, 2));

            float mn0 = fmaxf(mprev[h][0], mx0), mn1 = fmaxf(mprev[h][1], mx1);
            alpha[h][0] = __expf(mprev[h][0] - mn0);
            alpha[h][1] = __expf(mprev[h][1] - mn1);

            float ps0 = 0.f, ps1 = 0.f;
            #pragma unroll
            for (int nt = 0; nt < 4; nt++) {
                float e00 = __expf(s[h][nt][0] - mn0);
                float e01 = __expf(s[h][nt][1] - mn0);
                float e10 = __expf(s[h][nt][2] - mn1);
                float e11 = __expf(s[h][nt][3] - mn1);
                ps0 += e00 + e01;
                ps1 += e10 + e11;
                int r = h * 64 + warp * 16 + g;
                Ps[r][nt * 4 + tg]     = pack_half2(e00, e01);
                Ps[r + 8][nt * 4 + tg] = pack_half2(e10, e11);
            }
            lsum[h][0] = lsum[h][0] * alpha[h][0] + ps0;
            lsum[h][1] = lsum[h][1] * alpha[h][1] + ps1;
            mprev[h][0] = mn0; mprev[h][1] = mn1;
        }
        __syncwarp();   // P writes visible before ldmatrix reads (warp-local rows)

        // O = O*alpha + P V  (2 k16 steps over 32 keys)
        #pragma unroll
        for (int h = 0; h < 2; h++)
            #pragma unroll
            for (int nt = 0; nt < 8; nt++) {
                o[h][nt][0] *= alpha[h][0]; o[h][nt][1] *= alpha[h][0];
                o[h][nt][2] *= alpha[h][1]; o[h][nt][3] *= alpha[h][1];
            }
        #pragma unroll
        for (int ks = 0; ks < 2; ks++) {
            uint32_t vb[8][2];
            #pragma unroll
            for (int ntp = 0; ntp < 4; ntp++)
                ldsm_x4(vb[2 * ntp][0], vb[2 * ntp][1], vb[2 * ntp + 1][0], vb[2 * ntp + 1][1],
                        vS + ntp * 16 * 80 + ks * 32);
            #pragma unroll
            for (int h = 0; h < 2; h++) {
                uint32_t af[4];
                ldsm_x4(af[0], af[1], af[2], af[3],
                        pAddr0 + (h * 64 + warp * 16) * 80 + ks * 32);
                #pragma unroll
                for (int nt = 0; nt < 8; nt++)
                    mma_f16(o[h][nt], af, vb[nt][0], vb[nt][1]);
            }
        }
        __syncwarp();
    }

    #pragma unroll
    for (int h = 0; h < 2; h++) {
        float l0 = lsum[h][0], l1 = lsum[h][1];
        l0 += __shfl_xor_sync(0xffffffffu, l0, 1);
        l0 += __shfl_xor_sync(0xffffffffu, l0, 2);
        l1 += __shfl_xor_sync(0xffffffffu, l1, 1);
        l1 += __shfl_xor_sync(0xffffffffu, l1, 2);
        float inv0 = 1.0f / l0, inv1 = 1.0f / l1;

        int r0 = q0 + h * 64 + warp * 16 + g;
        #pragma unroll
        for (int nt = 0; nt < 8; nt++) {
            int c = qcol + nt * 8 + 2 * tg;
            *reinterpret_cast<__half2*>(out16 + (base + r0) * DD + c) =
                __floats2half2_rn(o[h][nt][0] * inv0, o[h][nt][1] * inv0);
            *reinterpret_cast<__half2*>(out16 + (base + r0 + 8) * DD + c) =
                __floats2half2_rn(o[h][nt][2] * inv1, o[h][nt][3] * inv1);
        }
    }
}

// ---------------- residual add + LayerNorm (fp32 + optional fp16 out) -----
__device__ __forceinline__ float block_reduce_256(float v, float* red) {
    __syncthreads();
    int t = threadIdx.x;
    #pragma unroll
    for (int o = 16; o > 0; o >>= 1) v += __shfl_down_sync(0xffffffffu, v, o);
    if ((t & 31) == 0) red[t >> 5] = v;
    __syncthreads();
    if (t < 8) {
        v = red[t];
        #pragma unroll
        for (int o = 4; o > 0; o >>= 1) v += __shfl_down_sync(0xffu, v, o);
        if (t == 0) red[0] = v;
    }
    __syncthreads();
    return red[0];
}

template<bool OUT16>
__global__ void add_ln_kernel(const float* __restrict__ A,
                              float* __restrict__ X,
                              __half* __restrict__ X16,
                              const float* __restrict__ g,
                              const float* __restrict__ bt) {
    __shared__ float red[32];
    int r = blockIdx.x, t = threadIdx.x;
    const float* a = A + (size_t)r * DD;
    float* x = X + (size_t)r * DD;
    int d0 = t * 4;
    float4 av = *reinterpret_cast<const float4*>(a + d0);
    float4 xv = *reinterpret_cast<const float4*>(x + d0);
    float v[4] = {av.x + xv.x, av.y + xv.y, av.z + xv.z, av.w + xv.w};
    float sum = v[0] + v[1] + v[2] + v[3];
    sum = block_reduce_256(sum, red);
    float mu = sum * (1.0f / DD);
    float vs = 0.f;
    #pragma unroll
    for (int i = 0; i < 4; i++) { float dl = v[i] - mu; vs += dl * dl; }
    vs = block_reduce_256(vs, red);
    float rs = rsqrtf(vs * (1.0f / DD) + 1e-5f);
    float o[4];
    #pragma unroll
    for (int i = 0; i < 4; i++)
        o[i] = (v[i] - mu) * rs * g[d0 + i] + bt[d0 + i];
    *reinterpret_cast<float4*>(x + d0) = make_float4(o[0], o[1], o[2], o[3]);
    if (OUT16) {
        __half* x16 = X16 + (size_t)r * DD + d0;
        *reinterpret_cast<__half2*>(x16)     = __floats2half2_rn(o[0], o[1]);
        *reinterpret_cast<__half2*>(x16 + 2) = __floats2half2_rn(o[2], o[3]);
    }
}

// ---------------- masked max-pool over sequence ----------------
__global__ void pool_partial_kernel(const float* __restrict__ X,
                                    const int* __restrict__ mask,
                                    float* __restrict__ part) {
    int b = blockIdx.y, ch = blockIdx.x;
    int d = threadIdx.x;
    float m = -INFINITY;
    for (int s = 0; s < 128; s++) {
        int srow = ch * 128 + s;
        float val = X[((size_t)b * SS + srow) * DD + d];
        if (mask[b * SS + srow] != 0) m = fmaxf(m, val);
    }
    part[((size_t)b * 16 + ch) * DD + d] = m;
}

__global__ void pool_final_kernel(const float* __restrict__ part,
                                  float* __restrict__ pooled) {
    int b = blockIdx.x, d = threadIdx.x;
    float m = -INFINITY;
    for (int c = 0; c < 16; c++)
        m = fmaxf(m, part[((size_t)b * 16 + c) * DD + d]);
    pooled[b * DD + d] = m;
}

// ---------------- small head FC ----------------
__global__ void head_fc_kernel(const float* __restrict__ in,
                               const float* __restrict__ W,
                               const float* __restrict__ bias,
                               float* __restrict__ out,
                               int K, int apply_gelu) {
    __shared__ float red[4];
    int n = blockIdx.x, b = blockIdx.y, t = threadIdx.x;
    int N = gridDim.x;
    const float* ip = in + (size_t)b * K;
    const float* wp = W + (size_t)n * K;
    float s = 0.f;
    for (int k = t; k < K; k += 128) s += ip[k] * wp[k];
    #pragma unroll
    for (int o = 16; o > 0; o >>= 1) s += __shfl_down_sync(0xffffffffu, s, o);
    if ((t & 31) == 0) red[t >> 5] = s;
    __syncthreads();
    if (t == 0) {
        float v = red[0] + red[1] + red[2] + red[3] + bias[n];
        if (apply_gelu) v = gelu_exact(v);
        out[b * N + n] = v;
    }
}

// ---------------- launch ----------------
extern "C" void kernel_launch(void* const* d_in, const int* in_sizes, int n_in,
                              void* d_out, int out_size) {
    const int*   x_ids  = (const int*)d_in[0];
    const int*   mask   = (const int*)d_in[1];
    const float* emb    = (const float*)d_in[2];
    const float* qkv_w  = (const float*)d_in[3];
    const float* fc_w   = (const float*)d_in[4];
    const float* fc_b   = (const float*)d_in[5];
    const float* ln1_g  = (const float*)d_in[6];
    const float* ln1_b  = (const float*)d_in[7];
    const float* ffn_w1 = (const float*)d_in[8];
    const float* ffn_b1 = (const float*)d_in[9];
    const float* ffn_w2 = (const float*)d_in[10];
    const float* ffn_b2 = (const float*)d_in[11];
    const float* ln2_g  = (const float*)d_in[12];
    const float* ln2_b  = (const float*)d_in[13];
    const float* pr_w1  = (const float*)d_in[14];
    const float* pr_b1  = (const float*)d_in[15];
    const float* pr_w2  = (const float*)d_in[16];
    const float* pr_b2  = (const float*)d_in[17];
    float* out = (float*)d_out;

    float *X, *O, *part, *pool, *hh;
    __half *X16, *QKV16, *Vt16, *AO16, *H16, *Wq16, *Wf16, *W116, *W216;
    cudaGetSymbolAddress((void**)&X,     g_X);
    cudaGetSymbolAddress((void**)&O,     g_O);
    cudaGetSymbolAddress((void**)&X16,   g_X16);
    cudaGetSymbolAddress((void**)&QKV16, g_QKV16);
    cudaGetSymbolAddress((void**)&Vt16,  g_Vt16);
    cudaGetSymbolAddress((void**)&AO16,  g_AO16);
    cudaGetSymbolAddress((void**)&H16,   g_H16);
    cudaGetSymbolAddress((void**)&Wq16,  g_Wq16);
    cudaGetSymbolAddress((void**)&Wf16,  g_Wf16);
    cudaGetSymbolAddress((void**)&W116,  g_W116);
    cudaGetSymbolAddress((void**)&W216,  g_W216);
    cudaGetSymbolAddress((void**)&part,  g_part);
    cudaGetSymbolAddress((void**)&pool,  g_pool);
    cudaGetSymbolAddress((void**)&hh,    g_hh);

    // 0. convert weights to fp16
    f2h_kernel<<<(3 * DD * DD / 4 + 255) / 256, 256>>>(qkv_w,  Wq16, 3 * DD * DD);
    f2h_kernel<<<(DD * DD / 4 + 255) / 256, 256>>>(fc_w,   Wf16, DD * DD);
    f2h_kernel<<<(FFN * DD / 4 + 255) / 256, 256>>>(ffn_w1, W116, FFN * DD);
    f2h_kernel<<<(DD * FFN / 4 + 255) / 256, 256>>>(ffn_w2, W216, DD * FFN);

    // 1. embedding + positional encoding (fp32 + fp16)
    embed_pe_kernel<<<(NTOK * (DD / 2)) / 256, 256>>>(x_ids, emb, X, X16);

    // 2. QKV projection -> fp16
    gemm_f16_kernel<0, true><<<dim3(3 * DD / 128, NTOK / 128), 128>>>(
        X16, Wq16, nullptr, nullptr, QKV16, NTOK, 3 * DD, DD);

    // 2b. transpose V
    transpose_v_kernel<<<dim3(SS / 32, HDIM / 32, BB * HH), dim3(32, 8)>>>(QKV16, Vt16);

    // 3. attention (fp16 MMA + ldmatrix)
    flash_f16_kernel<<<dim3(SS / 128, HH, BB), 128>>>(QKV16, Vt16, mask, AO16);

    // 4. output projection (+bias) -> fp32
    gemm_f16_kernel<1, false><<<dim3(DD / 128, NTOK / 128), 128>>>(
        AO16, Wf16, fc_b, O, nullptr, NTOK, DD, DD);

    // 5. residual + LN1 (fp32 X + fp16 copy)
    add_ln_kernel<true><<<NTOK, 256>>>(O, X, X16, ln1_g, ln1_b);

    // 6. FFN up (+bias, gelu) -> fp16
    gemm_f16_kernel<2, true><<<dim3(FFN / 128, NTOK / 128), 128>>>(
        X16, W116, ffn_b1, nullptr, H16, NTOK, FFN, DD);

    // 7. FFN down (+bias) -> fp32
    gemm_f16_kernel<1, false><<<dim3(DD / 128, NTOK / 128), 128>>>(
        H16, W216, ffn_b2, O, nullptr, NTOK, DD, FFN);

    // 8. residual + LN2 (fp32 only)
    add_ln_kernel<false><<<NTOK, 256>>>(O, X, nullptr, ln2_g, ln2_b);

    // 9. masked max-pool
    pool_partial_kernel<<<dim3(16, BB), 1024>>>(X, mask, part);
    pool_final_kernel<<<BB, 1024>>>(part, pool);

    // 10. prediction head
    head_fc_kernel<<<dim3(DD, BB), 128>>>(pool, pr_w1, pr_b1, hh, DD, 1);
    head_fc_kernel<<<dim3(10, BB), 128>>>(hh, pr_w2, pr_b2, out, DD, 0);
}